// round 10
// baseline (speedup 1.0000x reference)
#include <cuda_runtime.h>
#include <cuda_bf16.h>
#include <math.h>
#include <stdint.h>

#define BB 32
#define LL 196
#define DD 512
#define HH 8
#define DHH 64
#define MM (BB*LL)              // 6272

// ---------------- scratch (static device allocations; no malloc) -------------
__device__ float g_Q[MM*DD];
__device__ float g_K[MM*DD];
__device__ float g_V[MM*DD];
__device__ float g_ctx[MM*DD];
__device__ __nv_bfloat16 g_Qbf[MM*DD];
__device__ __nv_bfloat16 g_Kbf[MM*DD];
__device__ float g_rowmax[BB*BB*LL];
__device__ float g_colmax[BB*BB*LL];
// pre-split bf16 operands for the projection GEMM
__device__ __nv_bfloat16 g_Xhi[3*MM*DD];
__device__ __nv_bfloat16 g_Xlo[3*MM*DD];
__device__ __nv_bfloat16 g_Whi[3*DD*DD];
__device__ __nv_bfloat16 g_Wlo[3*DD*DD];

static const size_t OUT_CTX    = 0;
static const size_t OUT_LOGITS = (size_t)MM*DD;              // 3,211,264
static const size_t OUT_PROBS  = (size_t)MM*DD + BB*BB;      // 3,212,288

// float atomic max via signed/unsigned monotonicity trick (init = -inf)
__device__ __forceinline__ void atomicMaxF(float* addr, float v){
    if (v >= 0.0f) atomicMax((int*)addr, __float_as_int(v));
    else           atomicMin((unsigned int*)addr, __float_as_uint(v));
}

__device__ __forceinline__ void mma16816(float* d, const uint32_t* a,
                                         uint32_t b0, uint32_t b1){
    asm volatile("mma.sync.aligned.m16n8k16.row.col.f32.bf16.bf16.f32 "
        "{%0,%1,%2,%3}, {%4,%5,%6,%7}, {%8,%9}, {%0,%1,%2,%3};"
        : "+f"(d[0]), "+f"(d[1]), "+f"(d[2]), "+f"(d[3])
        : "r"(a[0]), "r"(a[1]), "r"(a[2]), "r"(a[3]), "r"(b0), "r"(b1));
}

__device__ __forceinline__ uint32_t packbf(__nv_bfloat16 a, __nv_bfloat16 b){
    __nv_bfloat162 t = __halves2bfloat162(a, b);
    return *(uint32_t*)&t;
}

__device__ __forceinline__ void cpasync16(uint32_t saddr, const void* gaddr){
    asm volatile("cp.async.cg.shared.global [%0], [%1], 16;"
                 :: "r"(saddr), "l"(gaddr) : "memory");
}
#define CP_COMMIT() asm volatile("cp.async.commit_group;" ::: "memory")
#define CP_WAIT1()  asm volatile("cp.async.wait_group 1;" ::: "memory")
#define CP_WAIT0()  asm volatile("cp.async.wait_group 0;" ::: "memory")

// ---------------- K0: init row/col max scratch -------------------------------
__global__ void init_kernel(){
    int i = blockIdx.x*blockDim.x + threadIdx.x;
    if (i < BB*BB*LL){ g_rowmax[i] = -INFINITY; g_colmax[i] = -INFINITY; }
}

// ---------------- K0b: fp32 -> bf16 hi/lo split (X and W) --------------------
__global__ __launch_bounds__(256) void split_x_kernel(
    const float* __restrict__ Xq, const float* __restrict__ Xk, const float* __restrict__ Xv){
    int z = blockIdx.z;
    const float* src = (z==0)? Xq : (z==1)? Xk : Xv;
    __nv_bfloat16* hi = g_Xhi + (size_t)z*MM*DD;
    __nv_bfloat16* lo = g_Xlo + (size_t)z*MM*DD;
    size_t i = ((size_t)blockIdx.x*256 + threadIdx.x)*4;
    if (i < (size_t)MM*DD){
        float4 f = *(const float4*)(src + i);
        __nv_bfloat16 hx=__float2bfloat16(f.x), hy=__float2bfloat16(f.y);
        __nv_bfloat16 hz=__float2bfloat16(f.z), hw=__float2bfloat16(f.w);
        uint2 vh; vh.x = packbf(hx,hy); vh.y = packbf(hz,hw);
        *(uint2*)(hi + i) = vh;
        uint2 vl;
        vl.x = packbf(__float2bfloat16(f.x-__bfloat162float(hx)),
                      __float2bfloat16(f.y-__bfloat162float(hy)));
        vl.y = packbf(__float2bfloat16(f.z-__bfloat162float(hz)),
                      __float2bfloat16(f.w-__bfloat162float(hw)));
        *(uint2*)(lo + i) = vl;
    }
}

__global__ __launch_bounds__(256) void split_w_kernel(
    const float* __restrict__ Wq, const float* __restrict__ Wk, const float* __restrict__ Wv){
    int z = blockIdx.z;
    const float* src = (z==0)? Wq : (z==1)? Wk : Wv;
    __nv_bfloat16* hi = g_Whi + (size_t)z*DD*DD;
    __nv_bfloat16* lo = g_Wlo + (size_t)z*DD*DD;
    size_t i = ((size_t)blockIdx.x*256 + threadIdx.x)*4;
    if (i < (size_t)DD*DD){
        float4 f = *(const float4*)(src + i);
        __nv_bfloat16 hx=__float2bfloat16(f.x), hy=__float2bfloat16(f.y);
        __nv_bfloat16 hz=__float2bfloat16(f.z), hw=__float2bfloat16(f.w);
        uint2 vh; vh.x = packbf(hx,hy); vh.y = packbf(hz,hw);
        *(uint2*)(hi + i) = vh;
        uint2 vl;
        vl.x = packbf(__float2bfloat16(f.x-__bfloat162float(hx)),
                      __float2bfloat16(f.y-__bfloat162float(hy)));
        vl.y = packbf(__float2bfloat16(f.z-__bfloat162float(hz)),
                      __float2bfloat16(f.w-__bfloat162float(hw)));
        *(uint2*)(lo + i) = vl;
    }
}

// ---------------- K1: QKV projection via bf16x3 split mma, cp.async 2-stage --
// C = X @ W^T + b.  x*w ~= xh*wh + xh*wl + xl*wh.  KC=32, 16 chunks.
#define PJ_STR 20                       // u32 per smem row (16 data + 4 pad)
#define PJ_TILE (128*PJ_STR)            // u32 per tile (2560)
#define PJ_SMEM (8*PJ_TILE*4)           // 2 stages x 4 tiles = 81920 B

__global__ __launch_bounds__(256, 2) void proj_kernel(
    const float* __restrict__ bq, const float* __restrict__ bk, const float* __restrict__ bv)
{
    int z = blockIdx.z;
    const float* bias = (z==0)? bq : (z==1)? bk : bv;
    float* dst = (z==0)? g_Q : (z==1)? g_K : g_V;
    __nv_bfloat16* dbf = (z==0)? g_Qbf : (z==1)? g_Kbf : (__nv_bfloat16*)0;

    extern __shared__ uint32_t psm[];
    uint32_t sb = (uint32_t)__cvta_generic_to_shared(psm);

    int tid = threadIdx.x;
    int lane = tid & 31, wid = tid >> 5;
    int g = lane >> 2, tg = lane & 3;
    int warpM = wid >> 1, warpN = wid & 1;

    int row0 = blockIdx.y * 128;
    int col0 = blockIdx.x * 128;

    const __nv_bfloat16* srcs[4] = {
        g_Xhi + (size_t)z*MM*DD + (size_t)row0*DD,
        g_Xlo + (size_t)z*MM*DD + (size_t)row0*DD,
        g_Whi + (size_t)z*DD*DD + (size_t)col0*DD,
        g_Wlo + (size_t)z*DD*DD + (size_t)col0*DD };

    float acc[2][8][4];
    #pragma unroll
    for (int mf=0;mf<2;mf++)
        #pragma unroll
        for (int nf=0;nf<8;nf++)
            #pragma unroll
            for (int q=0;q<4;q++) acc[mf][nf][q] = 0.0f;

    int r_ld = tid >> 2, j_ld = tid & 3;        // 256 thr = 64 rows x 4 segs; 2 passes/tile

    // prologue: chunk 0 -> stage 0
    #pragma unroll
    for (int t = 0; t < 4; t++){
        const __nv_bfloat16* s0 = srcs[t];
        #pragma unroll
        for (int h = 0; h < 2; h++){
            int r = r_ld + h*64;
            cpasync16(sb + (t*PJ_TILE + r*PJ_STR + j_ld*4)*4,
                      s0 + (size_t)r*DD + j_ld*8);
        }
    }
    CP_COMMIT();

    for (int c = 0; c < 16; c++){
        int st = c & 1;
        if (c + 1 < 16){
            int k0 = (c+1) * 32;
            int so = (st^1) * 4;
            #pragma unroll
            for (int t = 0; t < 4; t++){
                const __nv_bfloat16* s0 = srcs[t];
                #pragma unroll
                for (int h = 0; h < 2; h++){
                    int r = r_ld + h*64;
                    cpasync16(sb + ((so+t)*PJ_TILE + r*PJ_STR + j_ld*4)*4,
                              s0 + (size_t)r*DD + k0 + j_ld*8);
                }
            }
            CP_COMMIT();
            CP_WAIT1();
        } else {
            CP_WAIT0();
        }
        __syncthreads();

        const uint32_t* Ahi = psm + (st*4+0)*PJ_TILE;
        const uint32_t* Alo = psm + (st*4+1)*PJ_TILE;
        const uint32_t* Bhi = psm + (st*4+2)*PJ_TILE;
        const uint32_t* Blo = psm + (st*4+3)*PJ_TILE;

        #pragma unroll
        for (int ks = 0; ks < 2; ks++){
            uint32_t ahi[2][4], alo[2][4];
            #pragma unroll
            for (int mf=0; mf<2; mf++){
                int r = warpM*32 + mf*16 + g;
                const uint32_t* ah = &Ahi[r*PJ_STR + ks*8 + tg];
                ahi[mf][0] = ah[0]; ahi[mf][1] = ah[8*PJ_STR];
                ahi[mf][2] = ah[4]; ahi[mf][3] = ah[8*PJ_STR + 4];
                const uint32_t* al = &Alo[r*PJ_STR + ks*8 + tg];
                alo[mf][0] = al[0]; alo[mf][1] = al[8*PJ_STR];
                alo[mf][2] = al[4]; alo[mf][3] = al[8*PJ_STR + 4];
            }
            #pragma unroll
            for (int nf = 0; nf < 8; nf++){
                int n = warpN*64 + nf*8 + g;
                const uint32_t* bh = &Bhi[n*PJ_STR + ks*8 + tg];
                uint32_t bh0 = bh[0], bh1 = bh[4];
                const uint32_t* bl = &Blo[n*PJ_STR + ks*8 + tg];
                uint32_t bl0 = bl[0], bl1 = bl[4];
                #pragma unroll
                for (int mf=0; mf<2; mf++){
                    mma16816(acc[mf][nf], ahi[mf], bh0, bh1);
                    mma16816(acc[mf][nf], ahi[mf], bl0, bl1);
                    mma16816(acc[mf][nf], alo[mf], bh0, bh1);
                }
            }
        }
        __syncthreads();
    }

    #pragma unroll
    for (int mf = 0; mf < 2; mf++){
        int r0 = row0 + warpM*32 + mf*16 + g;
        #pragma unroll
        for (int nf = 0; nf < 8; nf++){
            int c0 = col0 + warpN*64 + nf*8 + tg*2;
            float b0 = bias[c0], b1 = bias[c0+1];
            float v00 = acc[mf][nf][0] + b0, v01 = acc[mf][nf][1] + b1;
            float v10 = acc[mf][nf][2] + b0, v11 = acc[mf][nf][3] + b1;
            dst[(size_t)r0*DD + c0]       = v00;
            dst[(size_t)r0*DD + c0 + 1]   = v01;
            dst[(size_t)(r0+8)*DD + c0]   = v10;
            dst[(size_t)(r0+8)*DD + c0+1] = v11;
            if (z < 2){
                dbf[(size_t)r0*DD + c0]       = __float2bfloat16(v00);
                dbf[(size_t)r0*DD + c0 + 1]   = __float2bfloat16(v01);
                dbf[(size_t)(r0+8)*DD + c0]   = __float2bfloat16(v10);
                dbf[(size_t)(r0+8)*DD + c0+1] = __float2bfloat16(v11);
            }
        }
    }
}

// ---------------- K2: retrieval GEMM via mma.sync, cp.async 2-stage ----------
#define RT_NT  112
#define RT_STR 20

__global__ __launch_bounds__(256) void retrieve_mma(){
    __shared__ uint32_t As[2][128*RT_STR];
    __shared__ uint32_t Bs[2][RT_NT*RT_STR];
    __shared__ float s_rowred[128];
    __shared__ float s_colred[RT_NT];

    uint32_t sbA = (uint32_t)__cvta_generic_to_shared(&As[0][0]);
    uint32_t sbB = (uint32_t)__cvta_generic_to_shared(&Bs[0][0]);

    int tid = threadIdx.x;
    int lane = tid & 31, wid = tid >> 5;
    int g = lane >> 2, tg = lane & 3;
    int warpM = wid >> 1, warpN = wid & 1;

    int bx = blockIdx.x;
    int p = bx >> 2;
    int mtile = (bx >> 1) & 1;
    int ntile = bx & 1;
    int a = p >> 5, b = p & 31;
    int row0 = mtile * 128;
    int ncol0 = ntile * RT_NT;

    if (tid < 128)   s_rowred[tid] = -INFINITY;
    if (tid < RT_NT) s_colred[tid] = -INFINITY;

    const __nv_bfloat16* Abase = g_Qbf + (size_t)(a*LL)*DD;
    const __nv_bfloat16* Bbase = g_Kbf + (size_t)(b*LL)*DD;

    float acc[2][7][4];
    #pragma unroll
    for (int mf=0;mf<2;mf++)
        #pragma unroll
        for (int nf=0;nf<7;nf++)
            #pragma unroll
            for (int q=0;q<4;q++) acc[mf][nf][q] = 0.0f;

    int r_ld = tid >> 2, j_ld = tid & 3;

    // prologue: chunk 0 -> stage 0
    {
        #pragma unroll
        for (int h = 0; h < 2; h++){
            int r = r_ld + h*64;
            int grow = row0 + r; if (grow > LL-1) grow = LL-1;
            cpasync16(sbA + (r*RT_STR + j_ld*4)*4, Abase + (size_t)grow*DD + j_ld*8);
        }
        {
            int r = r_ld;                       // rows 0..63
            int grow = ncol0 + r; if (grow > LL-1) grow = LL-1;
            cpasync16(sbB + (r*RT_STR + j_ld*4)*4, Bbase + (size_t)grow*DD + j_ld*8);
        }
        if (r_ld + 64 < RT_NT){
            int r = r_ld + 64;
            int grow = ncol0 + r; if (grow > LL-1) grow = LL-1;
            cpasync16(sbB + (r*RT_STR + j_ld*4)*4, Bbase + (size_t)grow*DD + j_ld*8);
        }
        CP_COMMIT();
    }

    for (int c = 0; c < 16; c++){
        int st = c & 1;
        if (c + 1 < 16){
            int k0 = (c+1) * 32;
            uint32_t dA = sbA + (st^1)*(128*RT_STR*4);
            uint32_t dB = sbB + (st^1)*(RT_NT*RT_STR*4);
            #pragma unroll
            for (int h = 0; h < 2; h++){
                int r = r_ld + h*64;
                int grow = row0 + r; if (grow > LL-1) grow = LL-1;
                cpasync16(dA + (r*RT_STR + j_ld*4)*4, Abase + (size_t)grow*DD + k0 + j_ld*8);
            }
            {
                int r = r_ld;
                int grow = ncol0 + r; if (grow > LL-1) grow = LL-1;
                cpasync16(dB + (r*RT_STR + j_ld*4)*4, Bbase + (size_t)grow*DD + k0 + j_ld*8);
            }
            if (r_ld + 64 < RT_NT){
                int r = r_ld + 64;
                int grow = ncol0 + r; if (grow > LL-1) grow = LL-1;
                cpasync16(dB + (r*RT_STR + j_ld*4)*4, Bbase + (size_t)grow*DD + k0 + j_ld*8);
            }
            CP_COMMIT();
            CP_WAIT1();
        } else {
            CP_WAIT0();
        }
        __syncthreads();

        const uint32_t* Ast = As[st];
        const uint32_t* Bst = Bs[st];

        #pragma unroll
        for (int ks = 0; ks < 2; ks++){
            uint32_t afr[2][4];
            #pragma unroll
            for (int mf=0; mf<2; mf++){
                int r = warpM*32 + mf*16 + g;
                const uint32_t* ap = &Ast[r*RT_STR + ks*8 + tg];
                afr[mf][0] = ap[0];
                afr[mf][1] = ap[8*RT_STR];
                afr[mf][2] = ap[4];
                afr[mf][3] = ap[8*RT_STR + 4];
            }
            #pragma unroll
            for (int nf = 0; nf < 7; nf++){
                int n = warpN*56 + nf*8 + g;
                const uint32_t* bp = &Bst[n*RT_STR + ks*8 + tg];
                uint32_t b0 = bp[0];
                uint32_t b1 = bp[4];
                mma16816(acc[0][nf], afr[0], b0, b1);
                mma16816(acc[1][nf], afr[1], b0, b1);
            }
        }
        __syncthreads();
    }

    #pragma unroll
    for (int mf = 0; mf < 2; mf++){
        int lr  = warpM*32 + mf*16 + g;
        int gr0 = row0 + lr;
        int gr8 = gr0 + 8;
        #pragma unroll
        for (int nf = 0; nf < 7; nf++){
            int lc = warpN*56 + nf*8 + tg*2;
            int gc = ncol0 + lc;
            float c0 = acc[mf][nf][0], c1 = acc[mf][nf][1];
            float c2 = acc[mf][nf][2], c3 = acc[mf][nf][3];
            bool cv0 = (gc < LL), cv1 = (gc+1 < LL);
            bool rv0 = (gr0 < LL), rv8 = (gr8 < LL);

            float rm0 = -INFINITY, rm8 = -INFINITY;
            if (cv0){ rm0 = fmaxf(rm0, c0); rm8 = fmaxf(rm8, c2); }
            if (cv1){ rm0 = fmaxf(rm0, c1); rm8 = fmaxf(rm8, c3); }
            atomicMaxF(&s_rowred[lr],     rm0);
            atomicMaxF(&s_rowred[lr + 8], rm8);

            float cm0 = -INFINITY, cm1 = -INFINITY;
            if (rv0){ cm0 = fmaxf(cm0, c0); cm1 = fmaxf(cm1, c1); }
            if (rv8){ cm0 = fmaxf(cm0, c2); cm1 = fmaxf(cm1, c3); }
            if (cv0) atomicMaxF(&s_colred[lc],     cm0);
            if (cv1) atomicMaxF(&s_colred[lc + 1], cm1);
        }
    }
    __syncthreads();

    if (tid < 128){
        int grow = row0 + tid;
        if (grow < LL) atomicMaxF(&g_rowmax[(size_t)p*LL + grow], s_rowred[tid]);
    }
    if (tid < RT_NT){
        int gcol = ncol0 + tid;
        if (gcol < LL) atomicMaxF(&g_colmax[(size_t)p*LL + gcol], s_colred[tid]);
    }
}

// ---------------- K3: logits reduce ------------------------------------------
__global__ __launch_bounds__(256) void logits_kernel(const float* __restrict__ ls,
                                                     float* __restrict__ out){
    int p = blockIdx.x;
    int t = threadIdx.x;
    float v = 0.0f;
    if (t < LL) v = g_rowmax[(size_t)p*LL + t] + g_colmax[(size_t)p*LL + t];
    #pragma unroll
    for (int o=16;o;o>>=1) v += __shfl_xor_sync(0xffffffffu, v, o);
    __shared__ float red[8];
    if ((t & 31) == 0) red[t >> 5] = v;
    __syncthreads();
    if (t == 0){
        float s = 0.0f;
        #pragma unroll
        for (int w=0; w<8; w++) s += red[w];
        out[p] = expf(ls[0]) * s / (2.0f * (float)LL);
    }
}

// ---------------- K4: self-attention, 4 rows/warp, shuffle-P ctx -------------
#define ATTN_SMEM ((196*68 + 196*64) * (int)sizeof(float))

__global__ __launch_bounds__(256, 2) void attn_kernel(float* __restrict__ out_probs){
    int h = blockIdx.x, b = blockIdx.y;
    extern __shared__ float sm[];
    float* Ks  = sm;                 // [196][68]
    float* Vs  = sm + 196*68;        // [196][64]

    int tid = threadIdx.x;
    int w = tid >> 5, lane = tid & 31;

    const float* Kg = g_K + (size_t)(b*LL)*DD + h*DHH;
    const float* Vg = g_V + (size_t)(b*LL)*DD + h*DHH;

    for (int i = tid; i < LL*16; i += 256){
        int m = i >> 4, d4 = (i & 15) * 4;
        *(float4*)&Ks[m*68 + d4] = *(const float4*)(Kg + (size_t)m*DD + d4);
        *(float4*)&Vs[m*64 + d4] = *(const float4*)(Vg + (size_t)m*DD + d4);
    }
    __syncthreads();

    const float* Qb = g_Q + (size_t)(b*LL)*DD + h*DHH;

    int mm[7]; bool valid[7];
    #pragma unroll
    for (int mi=0;mi<7;mi++){
        int m = lane + mi*32;
        valid[mi] = (m < LL);
        mm[mi] = valid[mi] ? m : (LL-1);
    }

    for (int l0 = w*4; l0 < LL; l0 += 32){
        float s[4][7];
        #pragma unroll
        for (int li=0;li<4;li++)
            #pragma unroll
            for (int mi=0;mi<7;mi++) s[li][mi] = 0.0f;

        for (int d4 = 0; d4 < DHH; d4 += 4){
            float4 q0 = *(const float4*)(Qb + (size_t)(l0+0)*DD + d4);
            float4 q1 = *(const float4*)(Qb + (size_t)(l0+1)*DD + d4);
            float4 q2 = *(const float4*)(Qb + (size_t)(l0+2)*DD + d4);
            float4 q3 = *(const float4*)(Qb + (size_t)(l0+3)*DD + d4);
            #pragma unroll
            for (int mi=0;mi<7;mi++){
                float4 kf = *(const float4*)&Ks[mm[mi]*68 + d4];
                s[0][mi] += q0.x*kf.x + q0.y*kf.y + q0.z*kf.z + q0.w*kf.w;
                s[1][mi] += q1.x*kf.x + q1.y*kf.y + q1.z*kf.z + q1.w*kf.w;
                s[2][mi] += q2.x*kf.x + q2.y*kf.y + q2.z*kf.z + q2.w*kf.w;
                s[3][mi] += q3.x*kf.x + q3.y*kf.y + q3.z*kf.z + q3.w*kf.w;
            }
        }

        #pragma unroll
        for (int li=0;li<4;li++){
            float mx = -INFINITY;
            #pragma unroll
            for (int mi=0;mi<7;mi++){
                s[li][mi] = valid[mi] ? s[li][mi]*0.125f : -INFINITY;
                mx = fmaxf(mx, s[li][mi]);
            }
            #pragma unroll
            for (int o=16;o;o>>=1) mx = fmaxf(mx, __shfl_xor_sync(0xffffffffu, mx, o));
            float sum = 0.0f;
            #pragma unroll
            for (int mi=0;mi<7;mi++){ float e = expf(s[li][mi]-mx); s[li][mi]=e; sum+=e; }
            #pragma unroll
            for (int o=16;o;o>>=1) sum += __shfl_xor_sync(0xffffffffu, sum, o);
            float inv = 1.0f / sum;

            float* pmrow = out_probs + (size_t)(b*LL + l0 + li)*LL;
            #pragma unroll
            for (int mi=0;mi<7;mi++){
                s[li][mi] *= inv;
                if (valid[mi]) atomicAdd(&pmrow[mm[mi]], s[li][mi] * 0.125f);
            }
        }

        float c0x=0.f,c0y=0.f,c1x=0.f,c1y=0.f,c2x=0.f,c2y=0.f,c3x=0.f,c3y=0.f;
        for (int mi=0;mi<7;mi++){
            float p0r = s[0][mi], p1r = s[1][mi], p2r = s[2][mi], p3r = s[3][mi];
            #pragma unroll
            for (int ls=0; ls<32; ls++){
                int m = mi*32 + ls;
                float p0 = __shfl_sync(0xffffffffu, p0r, ls);
                float p1 = __shfl_sync(0xffffffffu, p1r, ls);
                float p2 = __shfl_sync(0xffffffffu, p2r, ls);
                float p3 = __shfl_sync(0xffffffffu, p3r, ls);
                if (m < LL){
                    float2 v2 = *(const float2*)&Vs[m*64 + lane*2];
                    c0x += p0*v2.x; c0y += p0*v2.y;
                    c1x += p1*v2.x; c1y += p1*v2.y;
                    c2x += p2*v2.x; c2y += p2*v2.y;
                    c3x += p3*v2.x; c3y += p3*v2.y;
                }
            }
        }
        float* cr = g_ctx + (size_t)(b*LL + l0)*DD + h*DHH + lane*2;
        cr[0]      = c0x; cr[1]      = c0y;
        cr[DD]     = c1x; cr[DD+1]   = c1y;
        cr[2*DD]   = c2x; cr[2*DD+1] = c2y;
        cr[3*DD]   = c3x; cr[3*DD+1] = c3y;
    }
}

// ---------------- K5: residual + LayerNorm -----------------------------------
__global__ __launch_bounds__(128) void ln_kernel(const float* __restrict__ qin,
                                                 const float* __restrict__ gamma,
                                                 const float* __restrict__ beta,
                                                 float* __restrict__ out){
    int row = blockIdx.x;
    int t = threadIdx.x;
    const float* c = g_ctx + (size_t)row*DD;
    const float* q = qin   + (size_t)row*DD;
    __shared__ float red[4];

    float v[4]; float s = 0.0f;
    #pragma unroll
    for (int i=0;i<4;i++){ v[i] = c[t + i*128] + q[t + i*128]; s += v[i]; }
    #pragma unroll
    for (int o=16;o;o>>=1) s += __shfl_xor_sync(0xffffffffu, s, o);
    if ((t & 31) == 0) red[t>>5] = s;
    __syncthreads();
    float mu = (red[0]+red[1]+red[2]+red[3]) * (1.0f/DD);
    __syncthreads();

    float s2 = 0.0f;
    #pragma unroll
    for (int i=0;i<4;i++){ float d = v[i]-mu; s2 += d*d; }
    #pragma unroll
    for (int o=16;o;o>>=1) s2 += __shfl_xor_sync(0xffffffffu, s2, o);
    if ((t & 31) == 0) red[t>>5] = s2;
    __syncthreads();
    float var = (red[0]+red[1]+red[2]+red[3]) * (1.0f/DD);
    float invs = rsqrtf(var + 1e-6f);

    #pragma unroll
    for (int i=0;i<4;i++){
        int col = t + i*128;
        out[(size_t)row*DD + col] = (v[i]-mu)*invs*gamma[col] + beta[col];
    }
}

// ---------------- launch ------------------------------------------------------
extern "C" void kernel_launch(void* const* d_in, const int* in_sizes, int n_in,
                              void* d_out, int out_size)
{
    const float* q  = (const float*)d_in[0];
    const float* k  = (const float*)d_in[1];
    const float* v  = (const float*)d_in[2];
    const float* Wq = (const float*)d_in[3];
    const float* bq = (const float*)d_in[4];
    const float* Wk = (const float*)d_in[5];
    const float* bk = (const float*)d_in[6];
    const float* Wv = (const float*)d_in[7];
    const float* bv = (const float*)d_in[8];
    const float* gamma = (const float*)d_in[9];
    const float* beta  = (const float*)d_in[10];
    const float* ls    = (const float*)d_in[11];
    float* out = (float*)d_out;

    cudaFuncSetAttribute(attn_kernel, cudaFuncAttributeMaxDynamicSharedMemorySize, ATTN_SMEM);
    cudaFuncSetAttribute(proj_kernel, cudaFuncAttributeMaxDynamicSharedMemorySize, PJ_SMEM);

    init_kernel<<<(BB*BB*LL + 255)/256, 256>>>();
    cudaMemsetAsync(out + OUT_PROBS, 0, (size_t)BB*LL*LL*sizeof(float));

    split_x_kernel<<<dim3((MM*DD/4 + 255)/256, 1, 3), 256>>>(q, k, v);
    split_w_kernel<<<dim3((DD*DD/4 + 255)/256, 1, 3), 256>>>(Wq, Wk, Wv);

    proj_kernel<<<dim3(4, 49, 3), 256, PJ_SMEM>>>(bq, bk, bv);

    retrieve_mma<<<4096, 256>>>();

    attn_kernel<<<dim3(HH, BB), 256, ATTN_SMEM>>>(out + OUT_PROBS);

    logits_kernel<<<BB*BB, 256>>>(ls, out + OUT_LOGITS);

    ln_kernel<<<MM, 128>>>(q, gamma, beta, out + OUT_CTX);
}

// round 11
// speedup vs baseline: 1.0329x; 1.0329x over previous
#include <cuda_runtime.h>
#include <cuda_bf16.h>
#include <math.h>
#include <stdint.h>

#define BB 32
#define LL 196
#define DD 512
#define HH 8
#define DHH 64
#define MM (BB*LL)              // 6272

// ---------------- scratch (static device allocations; no malloc) -------------
__device__ float g_Q[MM*DD];
__device__ float g_K[MM*DD];
__device__ float g_V[MM*DD];
__device__ float g_ctx[MM*DD];
__device__ __nv_bfloat16 g_Qbf[MM*DD];
__device__ __nv_bfloat16 g_Kbf[MM*DD];
__device__ float g_rowmax[BB*BB*LL];
__device__ float g_colmax[BB*BB*LL];
// pre-split bf16 operands for the projection GEMM
__device__ __nv_bfloat16 g_Xhi[3*MM*DD];
__device__ __nv_bfloat16 g_Xlo[3*MM*DD];
__device__ __nv_bfloat16 g_Whi[3*DD*DD];
__device__ __nv_bfloat16 g_Wlo[3*DD*DD];

static const size_t OUT_CTX    = 0;
static const size_t OUT_LOGITS = (size_t)MM*DD;              // 3,211,264
static const size_t OUT_PROBS  = (size_t)MM*DD + BB*BB;      // 3,212,288

// float atomic max via signed/unsigned monotonicity trick (init = -inf)
__device__ __forceinline__ void atomicMaxF(float* addr, float v){
    if (v >= 0.0f) atomicMax((int*)addr, __float_as_int(v));
    else           atomicMin((unsigned int*)addr, __float_as_uint(v));
}

__device__ __forceinline__ void mma16816(float* d, const uint32_t* a,
                                         uint32_t b0, uint32_t b1){
    asm volatile("mma.sync.aligned.m16n8k16.row.col.f32.bf16.bf16.f32 "
        "{%0,%1,%2,%3}, {%4,%5,%6,%7}, {%8,%9}, {%0,%1,%2,%3};"
        : "+f"(d[0]), "+f"(d[1]), "+f"(d[2]), "+f"(d[3])
        : "r"(a[0]), "r"(a[1]), "r"(a[2]), "r"(a[3]), "r"(b0), "r"(b1));
}

__device__ __forceinline__ uint32_t packbf(__nv_bfloat16 a, __nv_bfloat16 b){
    __nv_bfloat162 t = __halves2bfloat162(a, b);
    return *(uint32_t*)&t;
}

__device__ __forceinline__ void cpasync16(uint32_t saddr, const void* gaddr){
    asm volatile("cp.async.cg.shared.global [%0], [%1], 16;"
                 :: "r"(saddr), "l"(gaddr) : "memory");
}
#define CP_COMMIT() asm volatile("cp.async.commit_group;" ::: "memory")
#define CP_WAIT1()  asm volatile("cp.async.wait_group 1;" ::: "memory")
#define CP_WAIT0()  asm volatile("cp.async.wait_group 0;" ::: "memory")

// ---------------- K0: init row/col max scratch -------------------------------
__global__ void init_kernel(){
    int i = blockIdx.x*blockDim.x + threadIdx.x;
    if (i < BB*BB*LL){ g_rowmax[i] = -INFINITY; g_colmax[i] = -INFINITY; }
}

// ---------------- K0b: fp32 -> bf16 hi/lo split (X and W) --------------------
__global__ __launch_bounds__(256) void split_x_kernel(
    const float* __restrict__ Xq, const float* __restrict__ Xk, const float* __restrict__ Xv){
    int z = blockIdx.z;
    const float* src = (z==0)? Xq : (z==1)? Xk : Xv;
    __nv_bfloat16* hi = g_Xhi + (size_t)z*MM*DD;
    __nv_bfloat16* lo = g_Xlo + (size_t)z*MM*DD;
    size_t i = ((size_t)blockIdx.x*256 + threadIdx.x)*4;
    if (i < (size_t)MM*DD){
        float4 f = *(const float4*)(src + i);
        __nv_bfloat16 hx=__float2bfloat16(f.x), hy=__float2bfloat16(f.y);
        __nv_bfloat16 hz=__float2bfloat16(f.z), hw=__float2bfloat16(f.w);
        uint2 vh; vh.x = packbf(hx,hy); vh.y = packbf(hz,hw);
        *(uint2*)(hi + i) = vh;
        uint2 vl;
        vl.x = packbf(__float2bfloat16(f.x-__bfloat162float(hx)),
                      __float2bfloat16(f.y-__bfloat162float(hy)));
        vl.y = packbf(__float2bfloat16(f.z-__bfloat162float(hz)),
                      __float2bfloat16(f.w-__bfloat162float(hw)));
        *(uint2*)(lo + i) = vl;
    }
}

__global__ __launch_bounds__(256) void split_w_kernel(
    const float* __restrict__ Wq, const float* __restrict__ Wk, const float* __restrict__ Wv){
    int z = blockIdx.z;
    const float* src = (z==0)? Wq : (z==1)? Wk : Wv;
    __nv_bfloat16* hi = g_Whi + (size_t)z*DD*DD;
    __nv_bfloat16* lo = g_Wlo + (size_t)z*DD*DD;
    size_t i = ((size_t)blockIdx.x*256 + threadIdx.x)*4;
    if (i < (size_t)DD*DD){
        float4 f = *(const float4*)(src + i);
        __nv_bfloat16 hx=__float2bfloat16(f.x), hy=__float2bfloat16(f.y);
        __nv_bfloat16 hz=__float2bfloat16(f.z), hw=__float2bfloat16(f.w);
        uint2 vh; vh.x = packbf(hx,hy); vh.y = packbf(hz,hw);
        *(uint2*)(hi + i) = vh;
        uint2 vl;
        vl.x = packbf(__float2bfloat16(f.x-__bfloat162float(hx)),
                      __float2bfloat16(f.y-__bfloat162float(hy)));
        vl.y = packbf(__float2bfloat16(f.z-__bfloat162float(hz)),
                      __float2bfloat16(f.w-__bfloat162float(hw)));
        *(uint2*)(lo + i) = vl;
    }
}

// ---------------- K1: QKV projection via bf16x3 split mma, cp.async 2-stage --
#define PJ_STR 20
#define PJ_TILE (128*PJ_STR)
#define PJ_SMEM (8*PJ_TILE*4)           // 81920 B

__global__ __launch_bounds__(256, 2) void proj_kernel(
    const float* __restrict__ bq, const float* __restrict__ bk, const float* __restrict__ bv)
{
    int z = blockIdx.z;
    const float* bias = (z==0)? bq : (z==1)? bk : bv;
    float* dst = (z==0)? g_Q : (z==1)? g_K : g_V;
    __nv_bfloat16* dbf = (z==0)? g_Qbf : (z==1)? g_Kbf : (__nv_bfloat16*)0;

    extern __shared__ uint32_t psm[];
    uint32_t sb = (uint32_t)__cvta_generic_to_shared(psm);

    int tid = threadIdx.x;
    int lane = tid & 31, wid = tid >> 5;
    int g = lane >> 2, tg = lane & 3;
    int warpM = wid >> 1, warpN = wid & 1;

    int row0 = blockIdx.y * 128;
    int col0 = blockIdx.x * 128;

    const __nv_bfloat16* srcs[4] = {
        g_Xhi + (size_t)z*MM*DD + (size_t)row0*DD,
        g_Xlo + (size_t)z*MM*DD + (size_t)row0*DD,
        g_Whi + (size_t)z*DD*DD + (size_t)col0*DD,
        g_Wlo + (size_t)z*DD*DD + (size_t)col0*DD };

    float acc[2][8][4];
    #pragma unroll
    for (int mf=0;mf<2;mf++)
        #pragma unroll
        for (int nf=0;nf<8;nf++)
            #pragma unroll
            for (int q=0;q<4;q++) acc[mf][nf][q] = 0.0f;

    int r_ld = tid >> 2, j_ld = tid & 3;

    #pragma unroll
    for (int t = 0; t < 4; t++){
        const __nv_bfloat16* s0 = srcs[t];
        #pragma unroll
        for (int h = 0; h < 2; h++){
            int r = r_ld + h*64;
            cpasync16(sb + (t*PJ_TILE + r*PJ_STR + j_ld*4)*4,
                      s0 + (size_t)r*DD + j_ld*8);
        }
    }
    CP_COMMIT();

    for (int c = 0; c < 16; c++){
        int st = c & 1;
        if (c + 1 < 16){
            int k0 = (c+1) * 32;
            int so = (st^1) * 4;
            #pragma unroll
            for (int t = 0; t < 4; t++){
                const __nv_bfloat16* s0 = srcs[t];
                #pragma unroll
                for (int h = 0; h < 2; h++){
                    int r = r_ld + h*64;
                    cpasync16(sb + ((so+t)*PJ_TILE + r*PJ_STR + j_ld*4)*4,
                              s0 + (size_t)r*DD + k0 + j_ld*8);
                }
            }
            CP_COMMIT();
            CP_WAIT1();
        } else {
            CP_WAIT0();
        }
        __syncthreads();

        const uint32_t* Ahi = psm + (st*4+0)*PJ_TILE;
        const uint32_t* Alo = psm + (st*4+1)*PJ_TILE;
        const uint32_t* Bhi = psm + (st*4+2)*PJ_TILE;
        const uint32_t* Blo = psm + (st*4+3)*PJ_TILE;

        #pragma unroll
        for (int ks = 0; ks < 2; ks++){
            uint32_t ahi[2][4], alo[2][4];
            #pragma unroll
            for (int mf=0; mf<2; mf++){
                int r = warpM*32 + mf*16 + g;
                const uint32_t* ah = &Ahi[r*PJ_STR + ks*8 + tg];
                ahi[mf][0] = ah[0]; ahi[mf][1] = ah[8*PJ_STR];
                ahi[mf][2] = ah[4]; ahi[mf][3] = ah[8*PJ_STR + 4];
                const uint32_t* al = &Alo[r*PJ_STR + ks*8 + tg];
                alo[mf][0] = al[0]; alo[mf][1] = al[8*PJ_STR];
                alo[mf][2] = al[4]; alo[mf][3] = al[8*PJ_STR + 4];
            }
            #pragma unroll
            for (int nf = 0; nf < 8; nf++){
                int n = warpN*64 + nf*8 + g;
                const uint32_t* bh = &Bhi[n*PJ_STR + ks*8 + tg];
                uint32_t bh0 = bh[0], bh1 = bh[4];
                const uint32_t* bl = &Blo[n*PJ_STR + ks*8 + tg];
                uint32_t bl0 = bl[0], bl1 = bl[4];
                #pragma unroll
                for (int mf=0; mf<2; mf++){
                    mma16816(acc[mf][nf], ahi[mf], bh0, bh1);
                    mma16816(acc[mf][nf], ahi[mf], bl0, bl1);
                    mma16816(acc[mf][nf], alo[mf], bh0, bh1);
                }
            }
        }
        __syncthreads();
    }

    #pragma unroll
    for (int mf = 0; mf < 2; mf++){
        int r0 = row0 + warpM*32 + mf*16 + g;
        #pragma unroll
        for (int nf = 0; nf < 8; nf++){
            int c0 = col0 + warpN*64 + nf*8 + tg*2;
            float b0 = bias[c0], b1 = bias[c0+1];
            float v00 = acc[mf][nf][0] + b0, v01 = acc[mf][nf][1] + b1;
            float v10 = acc[mf][nf][2] + b0, v11 = acc[mf][nf][3] + b1;
            dst[(size_t)r0*DD + c0]       = v00;
            dst[(size_t)r0*DD + c0 + 1]   = v01;
            dst[(size_t)(r0+8)*DD + c0]   = v10;
            dst[(size_t)(r0+8)*DD + c0+1] = v11;
            if (z < 2){
                dbf[(size_t)r0*DD + c0]       = __float2bfloat16(v00);
                dbf[(size_t)r0*DD + c0 + 1]   = __float2bfloat16(v01);
                dbf[(size_t)(r0+8)*DD + c0]   = __float2bfloat16(v10);
                dbf[(size_t)(r0+8)*DD + c0+1] = __float2bfloat16(v11);
            }
        }
    }
}

// ---------------- fused retrieve + attn bodies -------------------------------
#define RT_NT  112
#define RT_STR 36
#define ATTN_SMEM ((196*68 + 196*64) * (int)sizeof(float))   // 103,488 B

// ---- retrieve body: R8-proven KC=64 serial staging, smem from dynamic pool --
__device__ __forceinline__ void retrieve_body(int bx, char* smraw){
    uint32_t* As = (uint32_t*)smraw;                 // 128*36 u32
    uint32_t* Bs = As + 128*RT_STR;                  // 112*36 u32
    float* s_rowred = (float*)(Bs + RT_NT*RT_STR);   // 128 f
    float* s_colred = s_rowred + 128;                // 112 f

    int tid = threadIdx.x;
    int lane = tid & 31, wid = tid >> 5;
    int g = lane >> 2, tg = lane & 3;
    int warpM = wid >> 1, warpN = wid & 1;

    int p = bx >> 2;
    int mtile = (bx >> 1) & 1;
    int ntile = bx & 1;
    int a = p >> 5, b = p & 31;
    int row0 = mtile * 128;
    int ncol0 = ntile * RT_NT;

    if (tid < 128)   s_rowred[tid] = -INFINITY;
    if (tid < RT_NT) s_colred[tid] = -INFINITY;

    const __nv_bfloat16* Abase = g_Qbf + (size_t)(a*LL)*DD;
    const __nv_bfloat16* Bbase = g_Kbf + (size_t)(b*LL)*DD;

    float acc[2][7][4];
    #pragma unroll
    for (int mf=0;mf<2;mf++)
        #pragma unroll
        for (int nf=0;nf<7;nf++)
            #pragma unroll
            for (int q=0;q<4;q++) acc[mf][nf][q] = 0.0f;

    for (int c = 0; c < 8; c++){
        int k0 = c * 64;
        for (int i = tid; i < 128*8; i += 256){
            int r = i >> 3, j = i & 7;
            int grow = row0 + r; if (grow > LL-1) grow = LL-1;
            uint4 v = ((const uint4*)(Abase + (size_t)grow*DD + k0))[j];
            *(uint4*)&As[r*RT_STR + j*4] = v;
        }
        for (int i = tid; i < RT_NT*8; i += 256){
            int r = i >> 3, j = i & 7;
            int grow = ncol0 + r; if (grow > LL-1) grow = LL-1;
            uint4 v = ((const uint4*)(Bbase + (size_t)grow*DD + k0))[j];
            *(uint4*)&Bs[r*RT_STR + j*4] = v;
        }
        __syncthreads();

        #pragma unroll
        for (int ks = 0; ks < 4; ks++){
            uint32_t afr[2][4];
            #pragma unroll
            for (int mf=0; mf<2; mf++){
                int r = warpM*32 + mf*16 + g;
                const uint32_t* ap = &As[r*RT_STR + ks*8 + tg];
                afr[mf][0] = ap[0];
                afr[mf][1] = ap[8*RT_STR];
                afr[mf][2] = ap[4];
                afr[mf][3] = ap[8*RT_STR + 4];
            }
            #pragma unroll
            for (int nf = 0; nf < 7; nf++){
                int n = warpN*56 + nf*8 + g;
                const uint32_t* bp = &Bs[n*RT_STR + ks*8 + tg];
                uint32_t b0 = bp[0];
                uint32_t b1 = bp[4];
                mma16816(acc[0][nf], afr[0], b0, b1);
                mma16816(acc[1][nf], afr[1], b0, b1);
            }
        }
        __syncthreads();
    }

    #pragma unroll
    for (int mf = 0; mf < 2; mf++){
        int lr  = warpM*32 + mf*16 + g;
        int gr0 = row0 + lr;
        int gr8 = gr0 + 8;
        #pragma unroll
        for (int nf = 0; nf < 7; nf++){
            int lc = warpN*56 + nf*8 + tg*2;
            int gc = ncol0 + lc;
            float c0 = acc[mf][nf][0], c1 = acc[mf][nf][1];
            float c2 = acc[mf][nf][2], c3 = acc[mf][nf][3];
            bool cv0 = (gc < LL), cv1 = (gc+1 < LL);
            bool rv0 = (gr0 < LL), rv8 = (gr8 < LL);

            float rm0 = -INFINITY, rm8 = -INFINITY;
            if (cv0){ rm0 = fmaxf(rm0, c0); rm8 = fmaxf(rm8, c2); }
            if (cv1){ rm0 = fmaxf(rm0, c1); rm8 = fmaxf(rm8, c3); }
            atomicMaxF(&s_rowred[lr],     rm0);
            atomicMaxF(&s_rowred[lr + 8], rm8);

            float cm0 = -INFINITY, cm1 = -INFINITY;
            if (rv0){ cm0 = fmaxf(cm0, c0); cm1 = fmaxf(cm1, c1); }
            if (rv8){ cm0 = fmaxf(cm0, c2); cm1 = fmaxf(cm1, c3); }
            if (cv0) atomicMaxF(&s_colred[lc],     cm0);
            if (cv1) atomicMaxF(&s_colred[lc + 1], cm1);
        }
    }
    __syncthreads();

    if (tid < 128){
        int grow = row0 + tid;
        if (grow < LL) atomicMaxF(&g_rowmax[(size_t)p*LL + grow], s_rowred[tid]);
    }
    if (tid < RT_NT){
        int gcol = ncol0 + tid;
        if (gcol < LL) atomicMaxF(&g_colmax[(size_t)p*LL + gcol], s_colred[tid]);
    }
}

// ---- attn body: 4 rows/warp, shuffle-P ctx ----------------------------------
__device__ __forceinline__ void attn_body(int h, int b, float* sm,
                                          float* __restrict__ out_probs){
    float* Ks  = sm;                 // [196][68]
    float* Vs  = sm + 196*68;        // [196][64]

    int tid = threadIdx.x;
    int w = tid >> 5, lane = tid & 31;

    const float* Kg = g_K + (size_t)(b*LL)*DD + h*DHH;
    const float* Vg = g_V + (size_t)(b*LL)*DD + h*DHH;

    for (int i = tid; i < LL*16; i += 256){
        int m = i >> 4, d4 = (i & 15) * 4;
        *(float4*)&Ks[m*68 + d4] = *(const float4*)(Kg + (size_t)m*DD + d4);
        *(float4*)&Vs[m*64 + d4] = *(const float4*)(Vg + (size_t)m*DD + d4);
    }
    __syncthreads();

    const float* Qb = g_Q + (size_t)(b*LL)*DD + h*DHH;

    int mm[7]; bool valid[7];
    #pragma unroll
    for (int mi=0;mi<7;mi++){
        int m = lane + mi*32;
        valid[mi] = (m < LL);
        mm[mi] = valid[mi] ? m : (LL-1);
    }

    for (int l0 = w*4; l0 < LL; l0 += 32){
        float s[4][7];
        #pragma unroll
        for (int li=0;li<4;li++)
            #pragma unroll
            for (int mi=0;mi<7;mi++) s[li][mi] = 0.0f;

        for (int d4 = 0; d4 < DHH; d4 += 4){
            float4 q0 = *(const float4*)(Qb + (size_t)(l0+0)*DD + d4);
            float4 q1 = *(const float4*)(Qb + (size_t)(l0+1)*DD + d4);
            float4 q2 = *(const float4*)(Qb + (size_t)(l0+2)*DD + d4);
            float4 q3 = *(const float4*)(Qb + (size_t)(l0+3)*DD + d4);
            #pragma unroll
            for (int mi=0;mi<7;mi++){
                float4 kf = *(const float4*)&Ks[mm[mi]*68 + d4];
                s[0][mi] += q0.x*kf.x + q0.y*kf.y + q0.z*kf.z + q0.w*kf.w;
                s[1][mi] += q1.x*kf.x + q1.y*kf.y + q1.z*kf.z + q1.w*kf.w;
                s[2][mi] += q2.x*kf.x + q2.y*kf.y + q2.z*kf.z + q2.w*kf.w;
                s[3][mi] += q3.x*kf.x + q3.y*kf.y + q3.z*kf.z + q3.w*kf.w;
            }
        }

        #pragma unroll
        for (int li=0;li<4;li++){
            float mx = -INFINITY;
            #pragma unroll
            for (int mi=0;mi<7;mi++){
                s[li][mi] = valid[mi] ? s[li][mi]*0.125f : -INFINITY;
                mx = fmaxf(mx, s[li][mi]);
            }
            #pragma unroll
            for (int o=16;o;o>>=1) mx = fmaxf(mx, __shfl_xor_sync(0xffffffffu, mx, o));
            float sum = 0.0f;
            #pragma unroll
            for (int mi=0;mi<7;mi++){ float e = expf(s[li][mi]-mx); s[li][mi]=e; sum+=e; }
            #pragma unroll
            for (int o=16;o;o>>=1) sum += __shfl_xor_sync(0xffffffffu, sum, o);
            float inv = 1.0f / sum;

            float* pmrow = out_probs + (size_t)(b*LL + l0 + li)*LL;
            #pragma unroll
            for (int mi=0;mi<7;mi++){
                s[li][mi] *= inv;
                if (valid[mi]) atomicAdd(&pmrow[mm[mi]], s[li][mi] * 0.125f);
            }
        }

        float c0x=0.f,c0y=0.f,c1x=0.f,c1y=0.f,c2x=0.f,c2y=0.f,c3x=0.f,c3y=0.f;
        for (int mi=0;mi<7;mi++){
            float p0r = s[0][mi], p1r = s[1][mi], p2r = s[2][mi], p3r = s[3][mi];
            #pragma unroll
            for (int ls=0; ls<32; ls++){
                int m = mi*32 + ls;
                float p0 = __shfl_sync(0xffffffffu, p0r, ls);
                float p1 = __shfl_sync(0xffffffffu, p1r, ls);
                float p2 = __shfl_sync(0xffffffffu, p2r, ls);
                float p3 = __shfl_sync(0xffffffffu, p3r, ls);
                if (m < LL){
                    float2 v2 = *(const float2*)&Vs[m*64 + lane*2];
                    c0x += p0*v2.x; c0y += p0*v2.y;
                    c1x += p1*v2.x; c1y += p1*v2.y;
                    c2x += p2*v2.x; c2y += p2*v2.y;
                    c3x += p3*v2.x; c3y += p3*v2.y;
                }
            }
        }
        float* cr = g_ctx + (size_t)(b*LL + l0)*DD + h*DHH + lane*2;
        cr[0]      = c0x; cr[1]      = c0y;
        cr[DD]     = c1x; cr[DD+1]   = c1y;
        cr[2*DD]   = c2x; cr[2*DD+1] = c2y;
        cr[3*DD]   = c3x; cr[3*DD+1] = c3y;
    }
}

// ---- fused launch: attn CTAs first (long, 1 wave), then retrieve CTAs -------
__global__ __launch_bounds__(256, 2) void fused_ra(float* __restrict__ out_probs){
    extern __shared__ char fsm[];
    if (blockIdx.x < HH*BB){
        attn_body(blockIdx.x & 7, blockIdx.x >> 3, (float*)fsm, out_probs);
    } else {
        retrieve_body(blockIdx.x - HH*BB, fsm);
    }
}

// ---------------- K3: logits reduce ------------------------------------------
__global__ __launch_bounds__(256) void logits_kernel(const float* __restrict__ ls,
                                                     float* __restrict__ out){
    int p = blockIdx.x;
    int t = threadIdx.x;
    float v = 0.0f;
    if (t < LL) v = g_rowmax[(size_t)p*LL + t] + g_colmax[(size_t)p*LL + t];
    #pragma unroll
    for (int o=16;o;o>>=1) v += __shfl_xor_sync(0xffffffffu, v, o);
    __shared__ float red[8];
    if ((t & 31) == 0) red[t >> 5] = v;
    __syncthreads();
    if (t == 0){
        float s = 0.0f;
        #pragma unroll
        for (int w=0; w<8; w++) s += red[w];
        out[p] = expf(ls[0]) * s / (2.0f * (float)LL);
    }
}

// ---------------- K5: residual + LayerNorm -----------------------------------
__global__ __launch_bounds__(128) void ln_kernel(const float* __restrict__ qin,
                                                 const float* __restrict__ gamma,
                                                 const float* __restrict__ beta,
                                                 float* __restrict__ out){
    int row = blockIdx.x;
    int t = threadIdx.x;
    const float* c = g_ctx + (size_t)row*DD;
    const float* q = qin   + (size_t)row*DD;
    __shared__ float red[4];

    float v[4]; float s = 0.0f;
    #pragma unroll
    for (int i=0;i<4;i++){ v[i] = c[t + i*128] + q[t + i*128]; s += v[i]; }
    #pragma unroll
    for (int o=16;o;o>>=1) s += __shfl_xor_sync(0xffffffffu, s, o);
    if ((t & 31) == 0) red[t>>5] = s;
    __syncthreads();
    float mu = (red[0]+red[1]+red[2]+red[3]) * (1.0f/DD);
    __syncthreads();

    float s2 = 0.0f;
    #pragma unroll
    for (int i=0;i<4;i++){ float d = v[i]-mu; s2 += d*d; }
    #pragma unroll
    for (int o=16;o;o>>=1) s2 += __shfl_xor_sync(0xffffffffu, s2, o);
    if ((t & 31) == 0) red[t>>5] = s2;
    __syncthreads();
    float var = (red[0]+red[1]+red[2]+red[3]) * (1.0f/DD);
    float invs = rsqrtf(var + 1e-6f);

    #pragma unroll
    for (int i=0;i<4;i++){
        int col = t + i*128;
        out[(size_t)row*DD + col] = (v[i]-mu)*invs*gamma[col] + beta[col];
    }
}

// ---------------- launch ------------------------------------------------------
extern "C" void kernel_launch(void* const* d_in, const int* in_sizes, int n_in,
                              void* d_out, int out_size)
{
    const float* q  = (const float*)d_in[0];
    const float* k  = (const float*)d_in[1];
    const float* v  = (const float*)d_in[2];
    const float* Wq = (const float*)d_in[3];
    const float* bq = (const float*)d_in[4];
    const float* Wk = (const float*)d_in[5];
    const float* bk = (const float*)d_in[6];
    const float* Wv = (const float*)d_in[7];
    const float* bv = (const float*)d_in[8];
    const float* gamma = (const float*)d_in[9];
    const float* beta  = (const float*)d_in[10];
    const float* ls    = (const float*)d_in[11];
    float* out = (float*)d_out;

    cudaFuncSetAttribute(fused_ra,    cudaFuncAttributeMaxDynamicSharedMemorySize, ATTN_SMEM);
    cudaFuncSetAttribute(proj_kernel, cudaFuncAttributeMaxDynamicSharedMemorySize, PJ_SMEM);

    init_kernel<<<(BB*BB*LL + 255)/256, 256>>>();
    cudaMemsetAsync(out + OUT_PROBS, 0, (size_t)BB*LL*LL*sizeof(float));

    split_x_kernel<<<dim3((MM*DD/4 + 255)/256, 1, 3), 256>>>(q, k, v);
    split_w_kernel<<<dim3((DD*DD/4 + 255)/256, 1, 3), 256>>>(Wq, Wk, Wv);

    proj_kernel<<<dim3(4, 49, 3), 256, PJ_SMEM>>>(bq, bk, bv);

    fused_ra<<<HH*BB + 4096, 256, ATTN_SMEM>>>(out + OUT_PROBS);

    logits_kernel<<<BB*BB, 256>>>(ls, out + OUT_LOGITS);

    ln_kernel<<<MM, 128>>>(q, gamma, beta, out + OUT_CTX);
}

// round 14
// speedup vs baseline: 1.2024x; 1.1641x over previous
#include <cuda_runtime.h>
#include <cuda_bf16.h>
#include <math.h>
#include <stdint.h>

#define BB 32
#define LL 196
#define DD 512
#define HH 8
#define DHH 64
#define MM (BB*LL)              // 6272

// ---------------- scratch (static device allocations; no malloc) -------------
__device__ float g_Q[MM*DD];
__device__ float g_K[MM*DD];
__device__ float g_V[MM*DD];
__device__ float g_ctx[MM*DD];
__device__ __nv_bfloat16 g_Qbf[MM*DD];
__device__ __nv_bfloat16 g_Kbf[MM*DD];
__device__ float g_rowmax[BB*BB*LL];
__device__ float g_colmax[BB*BB*LL];
// pre-split bf16 operands for the projection GEMM
__device__ __nv_bfloat16 g_Xhi[3*MM*DD];
__device__ __nv_bfloat16 g_Xlo[3*MM*DD];
__device__ __nv_bfloat16 g_Whi[3*DD*DD];
__device__ __nv_bfloat16 g_Wlo[3*DD*DD];

static const size_t OUT_CTX    = 0;
static const size_t OUT_LOGITS = (size_t)MM*DD;              // 3,211,264
static const size_t OUT_PROBS  = (size_t)MM*DD + BB*BB;      // 3,212,288

// float atomic max via signed/unsigned monotonicity trick (init = -inf)
__device__ __forceinline__ void atomicMaxF(float* addr, float v){
    if (v >= 0.0f) atomicMax((int*)addr, __float_as_int(v));
    else           atomicMin((unsigned int*)addr, __float_as_uint(v));
}

__device__ __forceinline__ void mma16816(float* d, const uint32_t* a,
                                         uint32_t b0, uint32_t b1){
    asm volatile("mma.sync.aligned.m16n8k16.row.col.f32.bf16.bf16.f32 "
        "{%0,%1,%2,%3}, {%4,%5,%6,%7}, {%8,%9}, {%0,%1,%2,%3};"
        : "+f"(d[0]), "+f"(d[1]), "+f"(d[2]), "+f"(d[3])
        : "r"(a[0]), "r"(a[1]), "r"(a[2]), "r"(a[3]), "r"(b0), "r"(b1));
}

__device__ __forceinline__ void ldmA(uint32_t* r, uint32_t saddr){
    asm volatile("ldmatrix.sync.aligned.m8n8.x4.shared.b16 {%0,%1,%2,%3}, [%4];"
        : "=r"(r[0]), "=r"(r[1]), "=r"(r[2]), "=r"(r[3]) : "r"(saddr));
}
__device__ __forceinline__ void ldmB(uint32_t& r0, uint32_t& r1, uint32_t saddr){
    asm volatile("ldmatrix.sync.aligned.m8n8.x2.shared.b16 {%0,%1}, [%2];"
        : "=r"(r0), "=r"(r1) : "r"(saddr));
}

__device__ __forceinline__ uint32_t packbf(__nv_bfloat16 a, __nv_bfloat16 b){
    __nv_bfloat162 t = __halves2bfloat162(a, b);
    return *(uint32_t*)&t;
}

__device__ __forceinline__ void cpasync16(uint32_t saddr, const void* gaddr){
    asm volatile("cp.async.cg.shared.global [%0], [%1], 16;"
                 :: "r"(saddr), "l"(gaddr) : "memory");
}
#define CP_COMMIT() asm volatile("cp.async.commit_group;" ::: "memory")
#define CP_WAIT1()  asm volatile("cp.async.wait_group 1;" ::: "memory")
#define CP_WAIT0()  asm volatile("cp.async.wait_group 0;" ::: "memory")

// ---------------- K0: init row/col max scratch -------------------------------
__global__ void init_kernel(){
    int i = blockIdx.x*blockDim.x + threadIdx.x;
    if (i < BB*BB*LL){ g_rowmax[i] = -INFINITY; g_colmax[i] = -INFINITY; }
}

// ---------------- K0b: fp32 -> bf16 hi/lo split (X and W) --------------------
__global__ __launch_bounds__(256) void split_x_kernel(
    const float* __restrict__ Xq, const float* __restrict__ Xk, const float* __restrict__ Xv){
    int z = blockIdx.z;
    const float* src = (z==0)? Xq : (z==1)? Xk : Xv;
    __nv_bfloat16* hi = g_Xhi + (size_t)z*MM*DD;
    __nv_bfloat16* lo = g_Xlo + (size_t)z*MM*DD;
    size_t i = ((size_t)blockIdx.x*256 + threadIdx.x)*4;
    if (i < (size_t)MM*DD){
        float4 f = *(const float4*)(src + i);
        __nv_bfloat16 hx=__float2bfloat16(f.x), hy=__float2bfloat16(f.y);
        __nv_bfloat16 hz=__float2bfloat16(f.z), hw=__float2bfloat16(f.w);
        uint2 vh; vh.x = packbf(hx,hy); vh.y = packbf(hz,hw);
        *(uint2*)(hi + i) = vh;
        uint2 vl;
        vl.x = packbf(__float2bfloat16(f.x-__bfloat162float(hx)),
                      __float2bfloat16(f.y-__bfloat162float(hy)));
        vl.y = packbf(__float2bfloat16(f.z-__bfloat162float(hz)),
                      __float2bfloat16(f.w-__bfloat162float(hw)));
        *(uint2*)(lo + i) = vl;
    }
}

__global__ __launch_bounds__(256) void split_w_kernel(
    const float* __restrict__ Wq, const float* __restrict__ Wk, const float* __restrict__ Wv){
    int z = blockIdx.z;
    const float* src = (z==0)? Wq : (z==1)? Wk : Wv;
    __nv_bfloat16* hi = g_Whi + (size_t)z*DD*DD;
    __nv_bfloat16* lo = g_Wlo + (size_t)z*DD*DD;
    size_t i = ((size_t)blockIdx.x*256 + threadIdx.x)*4;
    if (i < (size_t)DD*DD){
        float4 f = *(const float4*)(src + i);
        __nv_bfloat16 hx=__float2bfloat16(f.x), hy=__float2bfloat16(f.y);
        __nv_bfloat16 hz=__float2bfloat16(f.z), hw=__float2bfloat16(f.w);
        uint2 vh; vh.x = packbf(hx,hy); vh.y = packbf(hz,hw);
        *(uint2*)(hi + i) = vh;
        uint2 vl;
        vl.x = packbf(__float2bfloat16(f.x-__bfloat162float(hx)),
                      __float2bfloat16(f.y-__bfloat162float(hy)));
        vl.y = packbf(__float2bfloat16(f.z-__bfloat162float(hz)),
                      __float2bfloat16(f.w-__bfloat162float(hw)));
        *(uint2*)(lo + i) = vl;
    }
}

// ---------------- K1: QKV projection via bf16x3 split mma --------------------
// cp.async 2-stage KC=32; fragment loads via ldmatrix.
#define PJ_STR 20
#define PJ_TILE (128*PJ_STR)
#define PJ_SMEM (8*PJ_TILE*4)           // 81920 B

__global__ __launch_bounds__(256, 2) void proj_kernel(
    const float* __restrict__ bq, const float* __restrict__ bk, const float* __restrict__ bv)
{
    int z = blockIdx.z;
    const float* bias = (z==0)? bq : (z==1)? bk : bv;
    float* dst = (z==0)? g_Q : (z==1)? g_K : g_V;
    __nv_bfloat16* dbf = (z==0)? g_Qbf : (z==1)? g_Kbf : (__nv_bfloat16*)0;

    extern __shared__ uint32_t psm[];
    uint32_t sb = (uint32_t)__cvta_generic_to_shared(psm);

    int tid = threadIdx.x;
    int lane = tid & 31, wid = tid >> 5;
    int g = lane >> 2, tg = lane & 3;
    int warpM = wid >> 1, warpN = wid & 1;

    int row0 = blockIdx.y * 128;
    int col0 = blockIdx.x * 128;

    const __nv_bfloat16* srcs[4] = {
        g_Xhi + (size_t)z*MM*DD + (size_t)row0*DD,
        g_Xlo + (size_t)z*MM*DD + (size_t)row0*DD,
        g_Whi + (size_t)z*DD*DD + (size_t)col0*DD,
        g_Wlo + (size_t)z*DD*DD + (size_t)col0*DD };

    float acc[2][8][4];
    #pragma unroll
    for (int mf=0;mf<2;mf++)
        #pragma unroll
        for (int nf=0;nf<8;nf++)
            #pragma unroll
            for (int q=0;q<4;q++) acc[mf][nf][q] = 0.0f;

    int r_ld = tid >> 2, j_ld = tid & 3;

    // ldmatrix per-lane address components (u32 units within a tile)
    int a_row  = warpM*32 + (lane & 15);
    int a_coff = (lane >> 4) * 4;
    int b_row  = warpN*64 + (lane & 7);
    int b_coff = ((lane >> 3) & 1) * 4;

    #pragma unroll
    for (int t = 0; t < 4; t++){
        const __nv_bfloat16* s0 = srcs[t];
        #pragma unroll
        for (int h = 0; h < 2; h++){
            int r = r_ld + h*64;
            cpasync16(sb + (t*PJ_TILE + r*PJ_STR + j_ld*4)*4,
                      s0 + (size_t)r*DD + j_ld*8);
        }
    }
    CP_COMMIT();

    for (int c = 0; c < 16; c++){
        int st = c & 1;
        if (c + 1 < 16){
            int k0 = (c+1) * 32;
            int so = (st^1) * 4;
            #pragma unroll
            for (int t = 0; t < 4; t++){
                const __nv_bfloat16* s0 = srcs[t];
                #pragma unroll
                for (int h = 0; h < 2; h++){
                    int r = r_ld + h*64;
                    cpasync16(sb + ((so+t)*PJ_TILE + r*PJ_STR + j_ld*4)*4,
                              s0 + (size_t)r*DD + k0 + j_ld*8);
                }
            }
            CP_COMMIT();
            CP_WAIT1();
        } else {
            CP_WAIT0();
        }
        __syncthreads();

        uint32_t sAhi = sb + ((st*4+0)*PJ_TILE)*4;
        uint32_t sAlo = sb + ((st*4+1)*PJ_TILE)*4;
        uint32_t sBhi = sb + ((st*4+2)*PJ_TILE)*4;
        uint32_t sBlo = sb + ((st*4+3)*PJ_TILE)*4;

        #pragma unroll
        for (int ks = 0; ks < 2; ks++){
            uint32_t ahi[2][4], alo[2][4];
            #pragma unroll
            for (int mf=0; mf<2; mf++){
                uint32_t off = (uint32_t)(((a_row + mf*16)*PJ_STR + a_coff + ks*8)*4);
                ldmA(ahi[mf], sAhi + off);
                ldmA(alo[mf], sAlo + off);
            }
            #pragma unroll
            for (int nf = 0; nf < 8; nf++){
                uint32_t boff = (uint32_t)(((b_row + nf*8)*PJ_STR + b_coff + ks*8)*4);
                uint32_t bh0, bh1, bl0, bl1;
                ldmB(bh0, bh1, sBhi + boff);
                ldmB(bl0, bl1, sBlo + boff);
                #pragma unroll
                for (int mf=0; mf<2; mf++){
                    mma16816(acc[mf][nf], ahi[mf], bh0, bh1);
                    mma16816(acc[mf][nf], ahi[mf], bl0, bl1);
                    mma16816(acc[mf][nf], alo[mf], bh0, bh1);
                }
            }
        }
        __syncthreads();
    }

    #pragma unroll
    for (int mf = 0; mf < 2; mf++){
        int r0 = row0 + warpM*32 + mf*16 + g;
        #pragma unroll
        for (int nf = 0; nf < 8; nf++){
            int c0 = col0 + warpN*64 + nf*8 + tg*2;
            float b0 = bias[c0], b1 = bias[c0+1];
            float v00 = acc[mf][nf][0] + b0, v01 = acc[mf][nf][1] + b1;
            float v10 = acc[mf][nf][2] + b0, v11 = acc[mf][nf][3] + b1;
            dst[(size_t)r0*DD + c0]       = v00;
            dst[(size_t)r0*DD + c0 + 1]   = v01;
            dst[(size_t)(r0+8)*DD + c0]   = v10;
            dst[(size_t)(r0+8)*DD + c0+1] = v11;
            if (z < 2){
                dbf[(size_t)r0*DD + c0]       = __float2bfloat16(v00);
                dbf[(size_t)r0*DD + c0 + 1]   = __float2bfloat16(v01);
                dbf[(size_t)(r0+8)*DD + c0]   = __float2bfloat16(v10);
                dbf[(size_t)(r0+8)*DD + c0+1] = __float2bfloat16(v11);
            }
        }
    }
}

// ---------------- fused retrieve + attn bodies -------------------------------
#define RT_NT  112
#define RT_STR 36
#define RT_STG ((128+RT_NT)*RT_STR)     // u32 per stage = 8640
#define ATTN_SMEM ((196*68 + 196*64) * (int)sizeof(float))   // 103,488 B

// ---- retrieve body: KC=64, cp.async 2-stage double buffer -------------------
__device__ __forceinline__ void retrieve_body(int bx, char* smraw){
    uint32_t* smu = (uint32_t*)smraw;
    uint32_t sbase = (uint32_t)__cvta_generic_to_shared(smraw);
    float* s_rowred = (float*)(smu + 2*RT_STG);      // 128 f
    float* s_colred = s_rowred + 128;                // 112 f

    int tid = threadIdx.x;
    int lane = tid & 31, wid = tid >> 5;
    int g = lane >> 2, tg = lane & 3;
    int warpM = wid >> 1, warpN = wid & 1;

    int p = bx >> 2;
    int mtile = (bx >> 1) & 1;
    int ntile = bx & 1;
    int a = p >> 5, b = p & 31;
    int row0 = mtile * 128;
    int ncol0 = ntile * RT_NT;

    if (tid < 128)   s_rowred[tid] = -INFINITY;
    if (tid < RT_NT) s_colred[tid] = -INFINITY;

    const __nv_bfloat16* Abase = g_Qbf + (size_t)(a*LL)*DD;
    const __nv_bfloat16* Bbase = g_Kbf + (size_t)(b*LL)*DD;

    float acc[2][7][4];
    #pragma unroll
    for (int mf=0;mf<2;mf++)
        #pragma unroll
        for (int nf=0;nf<7;nf++)
            #pragma unroll
            for (int q=0;q<4;q++) acc[mf][nf][q] = 0.0f;

    // stage loader: chunk c (KC=64) into stage s
    auto stage_load = [&](int c, int s){
        uint32_t dA = sbase + (uint32_t)(s*RT_STG*4);
        uint32_t dB = dA + 128*RT_STR*4;
        int k0 = c * 64;
        for (int i = tid; i < 128*8; i += 256){
            int r = i >> 3, j = i & 7;
            int grow = row0 + r; if (grow > LL-1) grow = LL-1;
            cpasync16(dA + (uint32_t)((r*RT_STR + j*4)*4),
                      Abase + (size_t)grow*DD + k0 + j*8);
        }
        for (int i = tid; i < RT_NT*8; i += 256){
            int r = i >> 3, j = i & 7;
            int grow = ncol0 + r; if (grow > LL-1) grow = LL-1;
            cpasync16(dB + (uint32_t)((r*RT_STR + j*4)*4),
                      Bbase + (size_t)grow*DD + k0 + j*8);
        }
        CP_COMMIT();
    };

    stage_load(0, 0);

    for (int c = 0; c < 8; c++){
        int st = c & 1;
        if (c + 1 < 8){
            stage_load(c+1, st^1);
            CP_WAIT1();
        } else {
            CP_WAIT0();
        }
        __syncthreads();

        const uint32_t* Ast = smu + st*RT_STG;
        const uint32_t* Bst = Ast + 128*RT_STR;

        #pragma unroll
        for (int ks = 0; ks < 4; ks++){
            uint32_t afr[2][4];
            #pragma unroll
            for (int mf=0; mf<2; mf++){
                int r = warpM*32 + mf*16 + g;
                const uint32_t* ap = &Ast[r*RT_STR + ks*8 + tg];
                afr[mf][0] = ap[0];
                afr[mf][1] = ap[8*RT_STR];
                afr[mf][2] = ap[4];
                afr[mf][3] = ap[8*RT_STR + 4];
            }
            #pragma unroll
            for (int nf = 0; nf < 7; nf++){
                int n = warpN*56 + nf*8 + g;
                const uint32_t* bp = &Bst[n*RT_STR + ks*8 + tg];
                uint32_t b0 = bp[0];
                uint32_t b1 = bp[4];
                mma16816(acc[0][nf], afr[0], b0, b1);
                mma16816(acc[1][nf], afr[1], b0, b1);
            }
        }
        __syncthreads();
    }

    #pragma unroll
    for (int mf = 0; mf < 2; mf++){
        int lr  = warpM*32 + mf*16 + g;
        int gr0 = row0 + lr;
        int gr8 = gr0 + 8;
        #pragma unroll
        for (int nf = 0; nf < 7; nf++){
            int lc = warpN*56 + nf*8 + tg*2;
            int gc = ncol0 + lc;
            float c0 = acc[mf][nf][0], c1 = acc[mf][nf][1];
            float c2 = acc[mf][nf][2], c3 = acc[mf][nf][3];
            bool cv0 = (gc < LL), cv1 = (gc+1 < LL);
            bool rv0 = (gr0 < LL), rv8 = (gr8 < LL);

            float rm0 = -INFINITY, rm8 = -INFINITY;
            if (cv0){ rm0 = fmaxf(rm0, c0); rm8 = fmaxf(rm8, c2); }
            if (cv1){ rm0 = fmaxf(rm0, c1); rm8 = fmaxf(rm8, c3); }
            atomicMaxF(&s_rowred[lr],     rm0);
            atomicMaxF(&s_rowred[lr + 8], rm8);

            float cm0 = -INFINITY, cm1 = -INFINITY;
            if (rv0){ cm0 = fmaxf(cm0, c0); cm1 = fmaxf(cm1, c1); }
            if (rv8){ cm0 = fmaxf(cm0, c2); cm1 = fmaxf(cm1, c3); }
            if (cv0) atomicMaxF(&s_colred[lc],     cm0);
            if (cv1) atomicMaxF(&s_colred[lc + 1], cm1);
        }
    }
    __syncthreads();

    if (tid < 128){
        int grow = row0 + tid;
        if (grow < LL) atomicMaxF(&g_rowmax[(size_t)p*LL + grow], s_rowred[tid]);
    }
    if (tid < RT_NT){
        int gcol = ncol0 + tid;
        if (gcol < LL) atomicMaxF(&g_colmax[(size_t)p*LL + gcol], s_colred[tid]);
    }
}

// ---- attn body: 4 rows/warp, shuffle-P ctx ----------------------------------
__device__ __forceinline__ void attn_body(int h, int b, float* sm,
                                          float* __restrict__ out_probs){
    float* Ks  = sm;                 // [196][68]
    float* Vs  = sm + 196*68;        // [196][64]

    int tid = threadIdx.x;
    int w = tid >> 5, lane = tid & 31;

    const float* Kg = g_K + (size_t)(b*LL)*DD + h*DHH;
    const float* Vg = g_V + (size_t)(b*LL)*DD + h*DHH;

    for (int i = tid; i < LL*16; i += 256){
        int m = i >> 4, d4 = (i & 15) * 4;
        *(float4*)&Ks[m*68 + d4] = *(const float4*)(Kg + (size_t)m*DD + d4);
        *(float4*)&Vs[m*64 + d4] = *(const float4*)(Vg + (size_t)m*DD + d4);
    }
    __syncthreads();

    const float* Qb = g_Q + (size_t)(b*LL)*DD + h*DHH;

    int mm[7]; bool valid[7];
    #pragma unroll
    for (int mi=0;mi<7;mi++){
        int m = lane + mi*32;
        valid[mi] = (m < LL);
        mm[mi] = valid[mi] ? m : (LL-1);
    }

    for (int l0 = w*4; l0 < LL; l0 += 32){
        float s[4][7];
        #pragma unroll
        for (int li=0;li<4;li++)
            #pragma unroll
            for (int mi=0;mi<7;mi++) s[li][mi] = 0.0f;

        for (int d4 = 0; d4 < DHH; d4 += 4){
            float4 q0 = *(const float4*)(Qb + (size_t)(l0+0)*DD + d4);
            float4 q1 = *(const float4*)(Qb + (size_t)(l0+1)*DD + d4);
            float4 q2 = *(const float4*)(Qb + (size_t)(l0+2)*DD + d4);
            float4 q3 = *(const float4*)(Qb + (size_t)(l0+3)*DD + d4);
            #pragma unroll
            for (int mi=0;mi<7;mi++){
                float4 kf = *(const float4*)&Ks[mm[mi]*68 + d4];
                s[0][mi] += q0.x*kf.x + q0.y*kf.y + q0.z*kf.z + q0.w*kf.w;
                s[1][mi] += q1.x*kf.x + q1.y*kf.y + q1.z*kf.z + q1.w*kf.w;
                s[2][mi] += q2.x*kf.x + q2.y*kf.y + q2.z*kf.z + q2.w*kf.w;
                s[3][mi] += q3.x*kf.x + q3.y*kf.y + q3.z*kf.z + q3.w*kf.w;
            }
        }

        #pragma unroll
        for (int li=0;li<4;li++){
            float mx = -INFINITY;
            #pragma unroll
            for (int mi=0;mi<7;mi++){
                s[li][mi] = valid[mi] ? s[li][mi]*0.125f : -INFINITY;
                mx = fmaxf(mx, s[li][mi]);
            }
            #pragma unroll
            for (int o=16;o;o>>=1) mx = fmaxf(mx, __shfl_xor_sync(0xffffffffu, mx, o));
            float sum = 0.0f;
            #pragma unroll
            for (int mi=0;mi<7;mi++){ float e = expf(s[li][mi]-mx); s[li][mi]=e; sum+=e; }
            #pragma unroll
            for (int o=16;o;o>>=1) sum += __shfl_xor_sync(0xffffffffu, sum, o);
            float inv = 1.0f / sum;

            float* pmrow = out_probs + (size_t)(b*LL + l0 + li)*LL;
            #pragma unroll
            for (int mi=0;mi<7;mi++){
                s[li][mi] *= inv;
                if (valid[mi]) atomicAdd(&pmrow[mm[mi]], s[li][mi] * 0.125f);
            }
        }

        float c0x=0.f,c0y=0.f,c1x=0.f,c1y=0.f,c2x=0.f,c2y=0.f,c3x=0.f,c3y=0.f;
        for (int mi=0;mi<7;mi++){
            float p0r = s[0][mi], p1r = s[1][mi], p2r = s[2][mi], p3r = s[3][mi];
            #pragma unroll
            for (int ls=0; ls<32; ls++){
                int m = mi*32 + ls;
                float p0 = __shfl_sync(0xffffffffu, p0r, ls);
                float p1 = __shfl_sync(0xffffffffu, p1r, ls);
                float p2 = __shfl_sync(0xffffffffu, p2r, ls);
                float p3 = __shfl_sync(0xffffffffu, p3r, ls);
                if (m < LL){
                    float2 v2 = *(const float2*)&Vs[m*64 + lane*2];
                    c0x += p0*v2.x; c0y += p0*v2.y;
                    c1x += p1*v2.x; c1y += p1*v2.y;
                    c2x += p2*v2.x; c2y += p2*v2.y;
                    c3x += p3*v2.x; c3y += p3*v2.y;
                }
            }
        }
        float* cr = g_ctx + (size_t)(b*LL + l0)*DD + h*DHH + lane*2;
        cr[0]      = c0x; cr[1]      = c0y;
        cr[DD]     = c1x; cr[DD+1]   = c1y;
        cr[2*DD]   = c2x; cr[2*DD+1] = c2y;
        cr[3*DD]   = c3x; cr[3*DD+1] = c3y;
    }
}

// ---- fused launch: attn CTAs first (long, 1 wave), then retrieve CTAs -------
__global__ __launch_bounds__(256, 2) void fused_ra(float* __restrict__ out_probs){
    extern __shared__ char fsm[];
    if (blockIdx.x < HH*BB){
        attn_body(blockIdx.x & 7, blockIdx.x >> 3, (float*)fsm, out_probs);
    } else {
        retrieve_body(blockIdx.x - HH*BB, fsm);
    }
}

// ---------------- K3: logits reduce ------------------------------------------
__global__ __launch_bounds__(256) void logits_kernel(const float* __restrict__ ls,
                                                     float* __restrict__ out){
    int p = blockIdx.x;
    int t = threadIdx.x;
    float v = 0.0f;
    if (t < LL) v = g_rowmax[(size_t)p*LL + t] + g_colmax[(size_t)p*LL + t];
    #pragma unroll
    for (int o=16;o;o>>=1) v += __shfl_xor_sync(0xffffffffu, v, o);
    __shared__ float red[8];
    if ((t & 31) == 0) red[t >> 5] = v;
    __syncthreads();
    if (t == 0){
        float s = 0.0f;
        #pragma unroll
        for (int w=0; w<8; w++) s += red[w];
        out[p] = expf(ls[0]) * s / (2.0f * (float)LL);
    }
}

// ---------------- K5: residual + LayerNorm -----------------------------------
__global__ __launch_bounds__(128) void ln_kernel(const float* __restrict__ qin,
                                                 const float* __restrict__ gamma,
                                                 const float* __restrict__ beta,
                                                 float* __restrict__ out){
    int row = blockIdx.x;
    int t = threadIdx.x;
    const float* c = g_ctx + (size_t)row*DD;
    const float* q = qin   + (size_t)row*DD;
    __shared__ float red[4];

    float v[4]; float s = 0.0f;
    #pragma unroll
    for (int i=0;i<4;i++){ v[i] = c[t + i*128] + q[t + i*128]; s += v[i]; }
    #pragma unroll
    for (int o=16;o;o>>=1) s += __shfl_xor_sync(0xffffffffu, s, o);
    if ((t & 31) == 0) red[t>>5] = s;
    __syncthreads();
    float mu = (red[0]+red[1]+red[2]+red[3]) * (1.0f/DD);
    __syncthreads();

    float s2 = 0.0f;
    #pragma unroll
    for (int i=0;i<4;i++){ float d = v[i]-mu; s2 += d*d; }
    #pragma unroll
    for (int o=16;o;o>>=1) s2 += __shfl_xor_sync(0xffffffffu, s2, o);
    if ((t & 31) == 0) red[t>>5] = s2;
    __syncthreads();
    float var = (red[0]+red[1]+red[2]+red[3]) * (1.0f/DD);
    float invs = rsqrtf(var + 1e-6f);

    #pragma unroll
    for (int i=0;i<4;i++){
        int col = t + i*128;
        out[(size_t)row*DD + col] = (v[i]-mu)*invs*gamma[col] + beta[col];
    }
}

// ---------------- launch ------------------------------------------------------
extern "C" void kernel_launch(void* const* d_in, const int* in_sizes, int n_in,
                              void* d_out, int out_size)
{
    const float* q  = (const float*)d_in[0];
    const float* k  = (const float*)d_in[1];
    const float* v  = (const float*)d_in[2];
    const float* Wq = (const float*)d_in[3];
    const float* bq = (const float*)d_in[4];
    const float* Wk = (const float*)d_in[5];
    const float* bk = (const float*)d_in[6];
    const float* Wv = (const float*)d_in[7];
    const float* bv = (const float*)d_in[8];
    const float* gamma = (const float*)d_in[9];
    const float* beta  = (const float*)d_in[10];
    const float* ls    = (const float*)d_in[11];
    float* out = (float*)d_out;

    cudaFuncSetAttribute(fused_ra,    cudaFuncAttributeMaxDynamicSharedMemorySize, ATTN_SMEM);
    cudaFuncSetAttribute(proj_kernel, cudaFuncAttributeMaxDynamicSharedMemorySize, PJ_SMEM);

    init_kernel<<<(BB*BB*LL + 255)/256, 256>>>();
    cudaMemsetAsync(out + OUT_PROBS, 0, (size_t)BB*LL*LL*sizeof(float));

    split_x_kernel<<<dim3((MM*DD/4 + 255)/256, 1, 3), 256>>>(q, k, v);
    split_w_kernel<<<dim3((DD*DD/4 + 255)/256, 1, 3), 256>>>(Wq, Wk, Wv);

    proj_kernel<<<dim3(4, 49, 3), 256, PJ_SMEM>>>(bq, bk, bv);

    fused_ra<<<HH*BB + 4096, 256, ATTN_SMEM>>>(out + OUT_PROBS);

    logits_kernel<<<BB*BB, 256>>>(ls, out + OUT_LOGITS);

    ln_kernel<<<MM, 128>>>(q, gamma, beta, out + OUT_CTX);
}

// round 15
// speedup vs baseline: 1.2198x; 1.0144x over previous
#include <cuda_runtime.h>
#include <cuda_bf16.h>
#include <math.h>
#include <stdint.h>

#define BB 32
#define LL 196
#define DD 512
#define HH 8
#define DHH 64
#define MM (BB*LL)              // 6272

// ---------------- scratch (static device allocations; no malloc) -------------
__device__ float g_Q[MM*DD];
__device__ float g_K[MM*DD];
__device__ float g_V[MM*DD];
__device__ float g_ctx[MM*DD];
__device__ __nv_bfloat16 g_Qbf[MM*DD];
__device__ __nv_bfloat16 g_Kbf[MM*DD];
__device__ float g_rowmax[BB*BB*LL];
__device__ float g_colmax[BB*BB*LL];
// pre-split bf16 operands for the projection GEMM
__device__ __nv_bfloat16 g_Xhi[3*MM*DD];
__device__ __nv_bfloat16 g_Xlo[3*MM*DD];
__device__ __nv_bfloat16 g_Whi[3*DD*DD];
__device__ __nv_bfloat16 g_Wlo[3*DD*DD];

static const size_t OUT_CTX    = 0;
static const size_t OUT_LOGITS = (size_t)MM*DD;              // 3,211,264
static const size_t OUT_PROBS  = (size_t)MM*DD + BB*BB;      // 3,212,288

// float atomic max via signed/unsigned monotonicity trick (init = -inf)
__device__ __forceinline__ void atomicMaxF(float* addr, float v){
    if (v >= 0.0f) atomicMax((int*)addr, __float_as_int(v));
    else           atomicMin((unsigned int*)addr, __float_as_uint(v));
}

__device__ __forceinline__ void mma16816(float* d, const uint32_t* a,
                                         uint32_t b0, uint32_t b1){
    asm volatile("mma.sync.aligned.m16n8k16.row.col.f32.bf16.bf16.f32 "
        "{%0,%1,%2,%3}, {%4,%5,%6,%7}, {%8,%9}, {%0,%1,%2,%3};"
        : "+f"(d[0]), "+f"(d[1]), "+f"(d[2]), "+f"(d[3])
        : "r"(a[0]), "r"(a[1]), "r"(a[2]), "r"(a[3]), "r"(b0), "r"(b1));
}

__device__ __forceinline__ void ldmA(uint32_t* r, uint32_t saddr){
    asm volatile("ldmatrix.sync.aligned.m8n8.x4.shared.b16 {%0,%1,%2,%3}, [%4];"
        : "=r"(r[0]), "=r"(r[1]), "=r"(r[2]), "=r"(r[3]) : "r"(saddr));
}
__device__ __forceinline__ void ldmB(uint32_t& r0, uint32_t& r1, uint32_t saddr){
    asm volatile("ldmatrix.sync.aligned.m8n8.x2.shared.b16 {%0,%1}, [%2];"
        : "=r"(r0), "=r"(r1) : "r"(saddr));
}

__device__ __forceinline__ uint32_t packbf(__nv_bfloat16 a, __nv_bfloat16 b){
    __nv_bfloat162 t = __halves2bfloat162(a, b);
    return *(uint32_t*)&t;
}

__device__ __forceinline__ void cpasync16(uint32_t saddr, const void* gaddr){
    asm volatile("cp.async.cg.shared.global [%0], [%1], 16;"
                 :: "r"(saddr), "l"(gaddr) : "memory");
}
#define CP_COMMIT() asm volatile("cp.async.commit_group;" ::: "memory")
#define CP_WAIT1()  asm volatile("cp.async.wait_group 1;" ::: "memory")
#define CP_WAIT0()  asm volatile("cp.async.wait_group 0;" ::: "memory")

// ---------------- K0: init row/col max scratch -------------------------------
__global__ void init_kernel(){
    int i = blockIdx.x*blockDim.x + threadIdx.x;
    if (i < BB*BB*LL){ g_rowmax[i] = -INFINITY; g_colmax[i] = -INFINITY; }
}

// ---------------- K0b: fp32 -> bf16 hi/lo split (X and W) --------------------
__global__ __launch_bounds__(256) void split_x_kernel(
    const float* __restrict__ Xq, const float* __restrict__ Xk, const float* __restrict__ Xv){
    int z = blockIdx.z;
    const float* src = (z==0)? Xq : (z==1)? Xk : Xv;
    __nv_bfloat16* hi = g_Xhi + (size_t)z*MM*DD;
    __nv_bfloat16* lo = g_Xlo + (size_t)z*MM*DD;
    size_t i = ((size_t)blockIdx.x*256 + threadIdx.x)*4;
    if (i < (size_t)MM*DD){
        float4 f = *(const float4*)(src + i);
        __nv_bfloat16 hx=__float2bfloat16(f.x), hy=__float2bfloat16(f.y);
        __nv_bfloat16 hz=__float2bfloat16(f.z), hw=__float2bfloat16(f.w);
        uint2 vh; vh.x = packbf(hx,hy); vh.y = packbf(hz,hw);
        *(uint2*)(hi + i) = vh;
        uint2 vl;
        vl.x = packbf(__float2bfloat16(f.x-__bfloat162float(hx)),
                      __float2bfloat16(f.y-__bfloat162float(hy)));
        vl.y = packbf(__float2bfloat16(f.z-__bfloat162float(hz)),
                      __float2bfloat16(f.w-__bfloat162float(hw)));
        *(uint2*)(lo + i) = vl;
    }
}

__global__ __launch_bounds__(256) void split_w_kernel(
    const float* __restrict__ Wq, const float* __restrict__ Wk, const float* __restrict__ Wv){
    int z = blockIdx.z;
    const float* src = (z==0)? Wq : (z==1)? Wk : Wv;
    __nv_bfloat16* hi = g_Whi + (size_t)z*DD*DD;
    __nv_bfloat16* lo = g_Wlo + (size_t)z*DD*DD;
    size_t i = ((size_t)blockIdx.x*256 + threadIdx.x)*4;
    if (i < (size_t)DD*DD){
        float4 f = *(const float4*)(src + i);
        __nv_bfloat16 hx=__float2bfloat16(f.x), hy=__float2bfloat16(f.y);
        __nv_bfloat16 hz=__float2bfloat16(f.z), hw=__float2bfloat16(f.w);
        uint2 vh; vh.x = packbf(hx,hy); vh.y = packbf(hz,hw);
        *(uint2*)(hi + i) = vh;
        uint2 vl;
        vl.x = packbf(__float2bfloat16(f.x-__bfloat162float(hx)),
                      __float2bfloat16(f.y-__bfloat162float(hy)));
        vl.y = packbf(__float2bfloat16(f.z-__bfloat162float(hz)),
                      __float2bfloat16(f.w-__bfloat162float(hw)));
        *(uint2*)(lo + i) = vl;
    }
}

// ---------------- K1: QKV projection via bf16x3 split mma --------------------
// cp.async 2-stage KC=32; fragment loads via ldmatrix.
#define PJ_STR 20
#define PJ_TILE (128*PJ_STR)
#define PJ_SMEM (8*PJ_TILE*4)           // 81920 B

__global__ __launch_bounds__(256, 2) void proj_kernel(
    const float* __restrict__ bq, const float* __restrict__ bk, const float* __restrict__ bv)
{
    int z = blockIdx.z;
    const float* bias = (z==0)? bq : (z==1)? bk : bv;
    float* dst = (z==0)? g_Q : (z==1)? g_K : g_V;
    __nv_bfloat16* dbf = (z==0)? g_Qbf : (z==1)? g_Kbf : (__nv_bfloat16*)0;

    extern __shared__ uint32_t psm[];
    uint32_t sb = (uint32_t)__cvta_generic_to_shared(psm);

    int tid = threadIdx.x;
    int lane = tid & 31, wid = tid >> 5;
    int g = lane >> 2, tg = lane & 3;
    int warpM = wid >> 1, warpN = wid & 1;

    int row0 = blockIdx.y * 128;
    int col0 = blockIdx.x * 128;

    const __nv_bfloat16* srcs[4] = {
        g_Xhi + (size_t)z*MM*DD + (size_t)row0*DD,
        g_Xlo + (size_t)z*MM*DD + (size_t)row0*DD,
        g_Whi + (size_t)z*DD*DD + (size_t)col0*DD,
        g_Wlo + (size_t)z*DD*DD + (size_t)col0*DD };

    float acc[2][8][4];
    #pragma unroll
    for (int mf=0;mf<2;mf++)
        #pragma unroll
        for (int nf=0;nf<8;nf++)
            #pragma unroll
            for (int q=0;q<4;q++) acc[mf][nf][q] = 0.0f;

    int r_ld = tid >> 2, j_ld = tid & 3;

    int a_row  = warpM*32 + (lane & 15);
    int a_coff = (lane >> 4) * 4;
    int b_row  = warpN*64 + (lane & 7);
    int b_coff = ((lane >> 3) & 1) * 4;

    #pragma unroll
    for (int t = 0; t < 4; t++){
        const __nv_bfloat16* s0 = srcs[t];
        #pragma unroll
        for (int h = 0; h < 2; h++){
            int r = r_ld + h*64;
            cpasync16(sb + (t*PJ_TILE + r*PJ_STR + j_ld*4)*4,
                      s0 + (size_t)r*DD + j_ld*8);
        }
    }
    CP_COMMIT();

    for (int c = 0; c < 16; c++){
        int st = c & 1;
        if (c + 1 < 16){
            int k0 = (c+1) * 32;
            int so = (st^1) * 4;
            #pragma unroll
            for (int t = 0; t < 4; t++){
                const __nv_bfloat16* s0 = srcs[t];
                #pragma unroll
                for (int h = 0; h < 2; h++){
                    int r = r_ld + h*64;
                    cpasync16(sb + ((so+t)*PJ_TILE + r*PJ_STR + j_ld*4)*4,
                              s0 + (size_t)r*DD + k0 + j_ld*8);
                }
            }
            CP_COMMIT();
            CP_WAIT1();
        } else {
            CP_WAIT0();
        }
        __syncthreads();

        uint32_t sAhi = sb + ((st*4+0)*PJ_TILE)*4;
        uint32_t sAlo = sb + ((st*4+1)*PJ_TILE)*4;
        uint32_t sBhi = sb + ((st*4+2)*PJ_TILE)*4;
        uint32_t sBlo = sb + ((st*4+3)*PJ_TILE)*4;

        #pragma unroll
        for (int ks = 0; ks < 2; ks++){
            uint32_t ahi[2][4], alo[2][4];
            #pragma unroll
            for (int mf=0; mf<2; mf++){
                uint32_t off = (uint32_t)(((a_row + mf*16)*PJ_STR + a_coff + ks*8)*4);
                ldmA(ahi[mf], sAhi + off);
                ldmA(alo[mf], sAlo + off);
            }
            #pragma unroll
            for (int nf = 0; nf < 8; nf++){
                uint32_t boff = (uint32_t)(((b_row + nf*8)*PJ_STR + b_coff + ks*8)*4);
                uint32_t bh0, bh1, bl0, bl1;
                ldmB(bh0, bh1, sBhi + boff);
                ldmB(bl0, bl1, sBlo + boff);
                #pragma unroll
                for (int mf=0; mf<2; mf++){
                    mma16816(acc[mf][nf], ahi[mf], bh0, bh1);
                    mma16816(acc[mf][nf], ahi[mf], bl0, bl1);
                    mma16816(acc[mf][nf], alo[mf], bh0, bh1);
                }
            }
        }
        __syncthreads();
    }

    #pragma unroll
    for (int mf = 0; mf < 2; mf++){
        int r0 = row0 + warpM*32 + mf*16 + g;
        #pragma unroll
        for (int nf = 0; nf < 8; nf++){
            int c0 = col0 + warpN*64 + nf*8 + tg*2;
            float b0 = bias[c0], b1 = bias[c0+1];
            float v00 = acc[mf][nf][0] + b0, v01 = acc[mf][nf][1] + b1;
            float v10 = acc[mf][nf][2] + b0, v11 = acc[mf][nf][3] + b1;
            dst[(size_t)r0*DD + c0]       = v00;
            dst[(size_t)r0*DD + c0 + 1]   = v01;
            dst[(size_t)(r0+8)*DD + c0]   = v10;
            dst[(size_t)(r0+8)*DD + c0+1] = v11;
            if (z < 2){
                dbf[(size_t)r0*DD + c0]       = __float2bfloat16(v00);
                dbf[(size_t)r0*DD + c0 + 1]   = __float2bfloat16(v01);
                dbf[(size_t)(r0+8)*DD + c0]   = __float2bfloat16(v10);
                dbf[(size_t)(r0+8)*DD + c0+1] = __float2bfloat16(v11);
            }
        }
    }
}

// ---------------- fused retrieve + attn bodies -------------------------------
// retrieve: CTA tile 128 x 208 (single N tile covers 196), KC=64, 2-stage cp.async
#define RT_NT  208
#define RT_STR 36
#define RT_ROWS (128 + RT_NT)           // 336 staged rows
#define RT_STG (RT_ROWS*RT_STR)         // u32 per stage = 12096 (48,384 B)
#define ATTN_SMEM ((196*68 + 196*64) * (int)sizeof(float))   // 103,488 B

__device__ __forceinline__ void retrieve_body(int bx, char* smraw){
    uint32_t* smu = (uint32_t*)smraw;
    uint32_t sbase = (uint32_t)__cvta_generic_to_shared(smraw);
    float* s_rowred = (float*)(smu + 2*RT_STG);      // 128 f
    float* s_colred = s_rowred + 128;                // 208 f

    int tid = threadIdx.x;
    int lane = tid & 31, wid = tid >> 5;
    int g = lane >> 2, tg = lane & 3;
    int warpM = wid >> 1, warpN = wid & 1;

    int p = bx >> 1;                     // pair 0..1023
    int mtile = bx & 1;
    int a = p >> 5, b = p & 31;
    int row0 = mtile * 128;

    if (tid < 128)   s_rowred[tid] = -INFINITY;
    if (tid < RT_NT) s_colred[tid] = -INFINITY;

    const __nv_bfloat16* Abase = g_Qbf + (size_t)(a*LL)*DD;
    const __nv_bfloat16* Bbase = g_Kbf + (size_t)(b*LL)*DD;

    float acc[2][13][4];
    #pragma unroll
    for (int mf=0;mf<2;mf++)
        #pragma unroll
        for (int nf=0;nf<13;nf++)
            #pragma unroll
            for (int q=0;q<4;q++) acc[mf][nf][q] = 0.0f;

    // stage loader: chunk c (KC=64) into stage s; rows 0..127 = A, 128.. = B
    auto stage_load = [&](int c, int s){
        uint32_t dst0 = sbase + (uint32_t)(s*RT_STG*4);
        int k0 = c * 64;
        for (int i = tid; i < RT_ROWS*8; i += 256){
            int r = i >> 3, j = i & 7;
            const __nv_bfloat16* src;
            if (r < 128){
                int grow = row0 + r; if (grow > LL-1) grow = LL-1;
                src = Abase + (size_t)grow*DD + k0 + j*8;
            } else {
                int grow = r - 128; if (grow > LL-1) grow = LL-1;
                src = Bbase + (size_t)grow*DD + k0 + j*8;
            }
            cpasync16(dst0 + (uint32_t)((r*RT_STR + j*4)*4), src);
        }
        CP_COMMIT();
    };

    stage_load(0, 0);

    for (int c = 0; c < 8; c++){
        int st = c & 1;
        if (c + 1 < 8){
            stage_load(c+1, st^1);
            CP_WAIT1();
        } else {
            CP_WAIT0();
        }
        __syncthreads();

        const uint32_t* Ast = smu + st*RT_STG;
        const uint32_t* Bst = Ast + 128*RT_STR;

        #pragma unroll
        for (int ks = 0; ks < 4; ks++){
            uint32_t afr[2][4];
            #pragma unroll
            for (int mf=0; mf<2; mf++){
                int r = warpM*32 + mf*16 + g;
                const uint32_t* ap = &Ast[r*RT_STR + ks*8 + tg];
                afr[mf][0] = ap[0];
                afr[mf][1] = ap[8*RT_STR];
                afr[mf][2] = ap[4];
                afr[mf][3] = ap[8*RT_STR + 4];
            }
            #pragma unroll
            for (int nf = 0; nf < 13; nf++){
                int n = warpN*104 + nf*8 + g;
                const uint32_t* bp = &Bst[n*RT_STR + ks*8 + tg];
                uint32_t b0 = bp[0];
                uint32_t b1 = bp[4];
                mma16816(acc[0][nf], afr[0], b0, b1);
                mma16816(acc[1][nf], afr[1], b0, b1);
            }
        }
        __syncthreads();
    }

    // ---- epilogue: element-wise masked max via shared atomics ----
    #pragma unroll
    for (int mf = 0; mf < 2; mf++){
        int lr  = warpM*32 + mf*16 + g;
        int gr0 = row0 + lr;
        int gr8 = gr0 + 8;
        #pragma unroll
        for (int nf = 0; nf < 13; nf++){
            int lc = warpN*104 + nf*8 + tg*2;     // = global column
            float c0 = acc[mf][nf][0], c1 = acc[mf][nf][1];
            float c2 = acc[mf][nf][2], c3 = acc[mf][nf][3];
            bool cv0 = (lc < LL), cv1 = (lc+1 < LL);
            bool rv0 = (gr0 < LL), rv8 = (gr8 < LL);

            float rm0 = -INFINITY, rm8 = -INFINITY;
            if (cv0){ rm0 = fmaxf(rm0, c0); rm8 = fmaxf(rm8, c2); }
            if (cv1){ rm0 = fmaxf(rm0, c1); rm8 = fmaxf(rm8, c3); }
            atomicMaxF(&s_rowred[lr],     rm0);
            atomicMaxF(&s_rowred[lr + 8], rm8);

            float cm0 = -INFINITY, cm1 = -INFINITY;
            if (rv0){ cm0 = fmaxf(cm0, c0); cm1 = fmaxf(cm1, c1); }
            if (rv8){ cm0 = fmaxf(cm0, c2); cm1 = fmaxf(cm1, c3); }
            if (cv0) atomicMaxF(&s_colred[lc],     cm0);
            if (cv1) atomicMaxF(&s_colred[lc + 1], cm1);
        }
    }
    __syncthreads();

    if (tid < 128){
        int grow = row0 + tid;
        if (grow < LL) atomicMaxF(&g_rowmax[(size_t)p*LL + grow], s_rowred[tid]);
    }
    if (tid < LL) atomicMaxF(&g_colmax[(size_t)p*LL + tid], s_colred[tid]);
}

// ---- attn body: 4 rows/warp, shuffle-P ctx ----------------------------------
__device__ __forceinline__ void attn_body(int h, int b, float* sm,
                                          float* __restrict__ out_probs){
    float* Ks  = sm;                 // [196][68]
    float* Vs  = sm + 196*68;        // [196][64]

    int tid = threadIdx.x;
    int w = tid >> 5, lane = tid & 31;

    const float* Kg = g_K + (size_t)(b*LL)*DD + h*DHH;
    const float* Vg = g_V + (size_t)(b*LL)*DD + h*DHH;

    for (int i = tid; i < LL*16; i += 256){
        int m = i >> 4, d4 = (i & 15) * 4;
        *(float4*)&Ks[m*68 + d4] = *(const float4*)(Kg + (size_t)m*DD + d4);
        *(float4*)&Vs[m*64 + d4] = *(const float4*)(Vg + (size_t)m*DD + d4);
    }
    __syncthreads();

    const float* Qb = g_Q + (size_t)(b*LL)*DD + h*DHH;

    int mm[7]; bool valid[7];
    #pragma unroll
    for (int mi=0;mi<7;mi++){
        int m = lane + mi*32;
        valid[mi] = (m < LL);
        mm[mi] = valid[mi] ? m : (LL-1);
    }

    for (int l0 = w*4; l0 < LL; l0 += 32){
        float s[4][7];
        #pragma unroll
        for (int li=0;li<4;li++)
            #pragma unroll
            for (int mi=0;mi<7;mi++) s[li][mi] = 0.0f;

        for (int d4 = 0; d4 < DHH; d4 += 4){
            float4 q0 = *(const float4*)(Qb + (size_t)(l0+0)*DD + d4);
            float4 q1 = *(const float4*)(Qb + (size_t)(l0+1)*DD + d4);
            float4 q2 = *(const float4*)(Qb + (size_t)(l0+2)*DD + d4);
            float4 q3 = *(const float4*)(Qb + (size_t)(l0+3)*DD + d4);
            #pragma unroll
            for (int mi=0;mi<7;mi++){
                float4 kf = *(const float4*)&Ks[mm[mi]*68 + d4];
                s[0][mi] += q0.x*kf.x + q0.y*kf.y + q0.z*kf.z + q0.w*kf.w;
                s[1][mi] += q1.x*kf.x + q1.y*kf.y + q1.z*kf.z + q1.w*kf.w;
                s[2][mi] += q2.x*kf.x + q2.y*kf.y + q2.z*kf.z + q2.w*kf.w;
                s[3][mi] += q3.x*kf.x + q3.y*kf.y + q3.z*kf.z + q3.w*kf.w;
            }
        }

        #pragma unroll
        for (int li=0;li<4;li++){
            float mx = -INFINITY;
            #pragma unroll
            for (int mi=0;mi<7;mi++){
                s[li][mi] = valid[mi] ? s[li][mi]*0.125f : -INFINITY;
                mx = fmaxf(mx, s[li][mi]);
            }
            #pragma unroll
            for (int o=16;o;o>>=1) mx = fmaxf(mx, __shfl_xor_sync(0xffffffffu, mx, o));
            float sum = 0.0f;
            #pragma unroll
            for (int mi=0;mi<7;mi++){ float e = expf(s[li][mi]-mx); s[li][mi]=e; sum+=e; }
            #pragma unroll
            for (int o=16;o;o>>=1) sum += __shfl_xor_sync(0xffffffffu, sum, o);
            float inv = 1.0f / sum;

            float* pmrow = out_probs + (size_t)(b*LL + l0 + li)*LL;
            #pragma unroll
            for (int mi=0;mi<7;mi++){
                s[li][mi] *= inv;
                if (valid[mi]) atomicAdd(&pmrow[mm[mi]], s[li][mi] * 0.125f);
            }
        }

        float c0x=0.f,c0y=0.f,c1x=0.f,c1y=0.f,c2x=0.f,c2y=0.f,c3x=0.f,c3y=0.f;
        for (int mi=0;mi<7;mi++){
            float p0r = s[0][mi], p1r = s[1][mi], p2r = s[2][mi], p3r = s[3][mi];
            #pragma unroll
            for (int ls=0; ls<32; ls++){
                int m = mi*32 + ls;
                float p0 = __shfl_sync(0xffffffffu, p0r, ls);
                float p1 = __shfl_sync(0xffffffffu, p1r, ls);
                float p2 = __shfl_sync(0xffffffffu, p2r, ls);
                float p3 = __shfl_sync(0xffffffffu, p3r, ls);
                if (m < LL){
                    float2 v2 = *(const float2*)&Vs[m*64 + lane*2];
                    c0x += p0*v2.x; c0y += p0*v2.y;
                    c1x += p1*v2.x; c1y += p1*v2.y;
                    c2x += p2*v2.x; c2y += p2*v2.y;
                    c3x += p3*v2.x; c3y += p3*v2.y;
                }
            }
        }
        float* cr = g_ctx + (size_t)(b*LL + l0)*DD + h*DHH + lane*2;
        cr[0]      = c0x; cr[1]      = c0y;
        cr[DD]     = c1x; cr[DD+1]   = c1y;
        cr[2*DD]   = c2x; cr[2*DD+1] = c2y;
        cr[3*DD]   = c3x; cr[3*DD+1] = c3y;
    }
}

// ---- fused launch: attn CTAs first (long, 1 wave), then retrieve CTAs -------
__global__ __launch_bounds__(256, 2) void fused_ra(float* __restrict__ out_probs){
    extern __shared__ char fsm[];
    if (blockIdx.x < HH*BB){
        attn_body(blockIdx.x & 7, blockIdx.x >> 3, (float*)fsm, out_probs);
    } else {
        retrieve_body(blockIdx.x - HH*BB, fsm);
    }
}

// ---------------- K3: logits reduce ------------------------------------------
__global__ __launch_bounds__(256) void logits_kernel(const float* __restrict__ ls,
                                                     float* __restrict__ out){
    int p = blockIdx.x;
    int t = threadIdx.x;
    float v = 0.0f;
    if (t < LL) v = g_rowmax[(size_t)p*LL + t] + g_colmax[(size_t)p*LL + t];
    #pragma unroll
    for (int o=16;o;o>>=1) v += __shfl_xor_sync(0xffffffffu, v, o);
    __shared__ float red[8];
    if ((t & 31) == 0) red[t >> 5] = v;
    __syncthreads();
    if (t == 0){
        float s = 0.0f;
        #pragma unroll
        for (int w=0; w<8; w++) s += red[w];
        out[p] = expf(ls[0]) * s / (2.0f * (float)LL);
    }
}

// ---------------- K5: residual + LayerNorm -----------------------------------
__global__ __launch_bounds__(128) void ln_kernel(const float* __restrict__ qin,
                                                 const float* __restrict__ gamma,
                                                 const float* __restrict__ beta,
                                                 float* __restrict__ out){
    int row = blockIdx.x;
    int t = threadIdx.x;
    const float* c = g_ctx + (size_t)row*DD;
    const float* q = qin   + (size_t)row*DD;
    __shared__ float red[4];

    float v[4]; float s = 0.0f;
    #pragma unroll
    for (int i=0;i<4;i++){ v[i] = c[t + i*128] + q[t + i*128]; s += v[i]; }
    #pragma unroll
    for (int o=16;o;o>>=1) s += __shfl_xor_sync(0xffffffffu, s, o);
    if ((t & 31) == 0) red[t>>5] = s;
    __syncthreads();
    float mu = (red[0]+red[1]+red[2]+red[3]) * (1.0f/DD);
    __syncthreads();

    float s2 = 0.0f;
    #pragma unroll
    for (int i=0;i<4;i++){ float d = v[i]-mu; s2 += d*d; }
    #pragma unroll
    for (int o=16;o;o>>=1) s2 += __shfl_xor_sync(0xffffffffu, s2, o);
    if ((t & 31) == 0) red[t>>5] = s2;
    __syncthreads();
    float var = (red[0]+red[1]+red[2]+red[3]) * (1.0f/DD);
    float invs = rsqrtf(var + 1e-6f);

    #pragma unroll
    for (int i=0;i<4;i++){
        int col = t + i*128;
        out[(size_t)row*DD + col] = (v[i]-mu)*invs*gamma[col] + beta[col];
    }
}

// ---------------- launch ------------------------------------------------------
extern "C" void kernel_launch(void* const* d_in, const int* in_sizes, int n_in,
                              void* d_out, int out_size)
{
    const float* q  = (const float*)d_in[0];
    const float* k  = (const float*)d_in[1];
    const float* v  = (const float*)d_in[2];
    const float* Wq = (const float*)d_in[3];
    const float* bq = (const float*)d_in[4];
    const float* Wk = (const float*)d_in[5];
    const float* bk = (const float*)d_in[6];
    const float* Wv = (const float*)d_in[7];
    const float* bv = (const float*)d_in[8];
    const float* gamma = (const float*)d_in[9];
    const float* beta  = (const float*)d_in[10];
    const float* ls    = (const float*)d_in[11];
    float* out = (float*)d_out;

    cudaFuncSetAttribute(fused_ra,    cudaFuncAttributeMaxDynamicSharedMemorySize, ATTN_SMEM);
    cudaFuncSetAttribute(proj_kernel, cudaFuncAttributeMaxDynamicSharedMemorySize, PJ_SMEM);

    init_kernel<<<(BB*BB*LL + 255)/256, 256>>>();
    cudaMemsetAsync(out + OUT_PROBS, 0, (size_t)BB*LL*LL*sizeof(float));

    split_x_kernel<<<dim3((MM*DD/4 + 255)/256, 1, 3), 256>>>(q, k, v);
    split_w_kernel<<<dim3((DD*DD/4 + 255)/256, 1, 3), 256>>>(Wq, Wk, Wv);

    proj_kernel<<<dim3(4, 49, 3), 256, PJ_SMEM>>>(bq, bk, bv);

    fused_ra<<<HH*BB + 2048, 256, ATTN_SMEM>>>(out + OUT_PROBS);

    logits_kernel<<<BB*BB, 256>>>(ls, out + OUT_LOGITS);

    ln_kernel<<<MM, 128>>>(q, gamma, beta, out + OUT_CTX);
}

// round 16
// speedup vs baseline: 1.2263x; 1.0054x over previous
#include <cuda_runtime.h>
#include <cuda_bf16.h>
#include <math.h>
#include <stdint.h>

#define BB 32
#define LL 196
#define DD 512
#define HH 8
#define DHH 64
#define MM (BB*LL)              // 6272

// ---------------- scratch (static device allocations; no malloc) -------------
__device__ float g_Q[MM*DD];
__device__ float g_K[MM*DD];
__device__ float g_V[MM*DD];
__device__ float g_ctx[MM*DD];
__device__ __nv_bfloat16 g_Qbf[MM*DD];
__device__ __nv_bfloat16 g_Kbf[MM*DD];
__device__ float g_rowmax[BB*BB*LL];
__device__ float g_colmax[BB*BB*LL];
// pre-split bf16 operands for the projection GEMM
__device__ __nv_bfloat16 g_Xhi[3*MM*DD];
__device__ __nv_bfloat16 g_Xlo[3*MM*DD];
__device__ __nv_bfloat16 g_Whi[3*DD*DD];
__device__ __nv_bfloat16 g_Wlo[3*DD*DD];

static const size_t OUT_CTX    = 0;
static const size_t OUT_LOGITS = (size_t)MM*DD;              // 3,211,264
static const size_t OUT_PROBS  = (size_t)MM*DD + BB*BB;      // 3,212,288

// float atomic max via signed/unsigned monotonicity trick (init = -inf)
__device__ __forceinline__ void atomicMaxF(float* addr, float v){
    if (v >= 0.0f) atomicMax((int*)addr, __float_as_int(v));
    else           atomicMin((unsigned int*)addr, __float_as_uint(v));
}

__device__ __forceinline__ void mma16816(float* d, const uint32_t* a,
                                         uint32_t b0, uint32_t b1){
    asm volatile("mma.sync.aligned.m16n8k16.row.col.f32.bf16.bf16.f32 "
        "{%0,%1,%2,%3}, {%4,%5,%6,%7}, {%8,%9}, {%0,%1,%2,%3};"
        : "+f"(d[0]), "+f"(d[1]), "+f"(d[2]), "+f"(d[3])
        : "r"(a[0]), "r"(a[1]), "r"(a[2]), "r"(a[3]), "r"(b0), "r"(b1));
}

__device__ __forceinline__ void ldmA(uint32_t* r, uint32_t saddr){
    asm volatile("ldmatrix.sync.aligned.m8n8.x4.shared.b16 {%0,%1,%2,%3}, [%4];"
        : "=r"(r[0]), "=r"(r[1]), "=r"(r[2]), "=r"(r[3]) : "r"(saddr));
}
__device__ __forceinline__ void ldmB(uint32_t& r0, uint32_t& r1, uint32_t saddr){
    asm volatile("ldmatrix.sync.aligned.m8n8.x2.shared.b16 {%0,%1}, [%2];"
        : "=r"(r0), "=r"(r1) : "r"(saddr));
}

__device__ __forceinline__ uint32_t packbf(__nv_bfloat16 a, __nv_bfloat16 b){
    __nv_bfloat162 t = __halves2bfloat162(a, b);
    return *(uint32_t*)&t;
}

__device__ __forceinline__ void cpasync16(uint32_t saddr, const void* gaddr){
    asm volatile("cp.async.cg.shared.global [%0], [%1], 16;"
                 :: "r"(saddr), "l"(gaddr) : "memory");
}
#define CP_COMMIT() asm volatile("cp.async.commit_group;" ::: "memory")
#define CP_WAIT0()  asm volatile("cp.async.wait_group 0;" ::: "memory")

// ---------------- K0: init row/col max scratch -------------------------------
__global__ void init_kernel(){
    int i = blockIdx.x*blockDim.x + threadIdx.x;
    if (i < BB*BB*LL){ g_rowmax[i] = -INFINITY; g_colmax[i] = -INFINITY; }
}

// ---------------- K0b: fp32 -> bf16 hi/lo split (X and W) --------------------
__global__ __launch_bounds__(256) void split_x_kernel(
    const float* __restrict__ Xq, const float* __restrict__ Xk, const float* __restrict__ Xv){
    int z = blockIdx.z;
    const float* src = (z==0)? Xq : (z==1)? Xk : Xv;
    __nv_bfloat16* hi = g_Xhi + (size_t)z*MM*DD;
    __nv_bfloat16* lo = g_Xlo + (size_t)z*MM*DD;
    size_t i = ((size_t)blockIdx.x*256 + threadIdx.x)*4;
    if (i < (size_t)MM*DD){
        float4 f = *(const float4*)(src + i);
        __nv_bfloat16 hx=__float2bfloat16(f.x), hy=__float2bfloat16(f.y);
        __nv_bfloat16 hz=__float2bfloat16(f.z), hw=__float2bfloat16(f.w);
        uint2 vh; vh.x = packbf(hx,hy); vh.y = packbf(hz,hw);
        *(uint2*)(hi + i) = vh;
        uint2 vl;
        vl.x = packbf(__float2bfloat16(f.x-__bfloat162float(hx)),
                      __float2bfloat16(f.y-__bfloat162float(hy)));
        vl.y = packbf(__float2bfloat16(f.z-__bfloat162float(hz)),
                      __float2bfloat16(f.w-__bfloat162float(hw)));
        *(uint2*)(lo + i) = vl;
    }
}

__global__ __launch_bounds__(256) void split_w_kernel(
    const float* __restrict__ Wq, const float* __restrict__ Wk, const float* __restrict__ Wv){
    int z = blockIdx.z;
    const float* src = (z==0)? Wq : (z==1)? Wk : Wv;
    __nv_bfloat16* hi = g_Whi + (size_t)z*DD*DD;
    __nv_bfloat16* lo = g_Wlo + (size_t)z*DD*DD;
    size_t i = ((size_t)blockIdx.x*256 + threadIdx.x)*4;
    if (i < (size_t)DD*DD){
        float4 f = *(const float4*)(src + i);
        __nv_bfloat16 hx=__float2bfloat16(f.x), hy=__float2bfloat16(f.y);
        __nv_bfloat16 hz=__float2bfloat16(f.z), hw=__float2bfloat16(f.w);
        uint2 vh; vh.x = packbf(hx,hy); vh.y = packbf(hz,hw);
        *(uint2*)(hi + i) = vh;
        uint2 vl;
        vl.x = packbf(__float2bfloat16(f.x-__bfloat162float(hx)),
                      __float2bfloat16(f.y-__bfloat162float(hy)));
        vl.y = packbf(__float2bfloat16(f.z-__bfloat162float(hz)),
                      __float2bfloat16(f.w-__bfloat162float(hw)));
        *(uint2*)(lo + i) = vl;
    }
}

// ---------------- K1: QKV projection via bf16x3 split mma --------------------
// cp.async 2-stage KC=32; ONE barrier per chunk (wait -> sync -> load-next -> compute).
#define PJ_STR 20
#define PJ_TILE (128*PJ_STR)
#define PJ_SMEM (8*PJ_TILE*4)           // 81920 B

__global__ __launch_bounds__(256, 2) void proj_kernel(
    const float* __restrict__ bq, const float* __restrict__ bk, const float* __restrict__ bv)
{
    int z = blockIdx.z;
    const float* bias = (z==0)? bq : (z==1)? bk : bv;
    float* dst = (z==0)? g_Q : (z==1)? g_K : g_V;
    __nv_bfloat16* dbf = (z==0)? g_Qbf : (z==1)? g_Kbf : (__nv_bfloat16*)0;

    extern __shared__ uint32_t psm[];
    uint32_t sb = (uint32_t)__cvta_generic_to_shared(psm);

    int tid = threadIdx.x;
    int lane = tid & 31, wid = tid >> 5;
    int g = lane >> 2, tg = lane & 3;
    int warpM = wid >> 1, warpN = wid & 1;

    int row0 = blockIdx.y * 128;
    int col0 = blockIdx.x * 128;

    const __nv_bfloat16* srcs[4] = {
        g_Xhi + (size_t)z*MM*DD + (size_t)row0*DD,
        g_Xlo + (size_t)z*MM*DD + (size_t)row0*DD,
        g_Whi + (size_t)z*DD*DD + (size_t)col0*DD,
        g_Wlo + (size_t)z*DD*DD + (size_t)col0*DD };

    float acc[2][8][4];
    #pragma unroll
    for (int mf=0;mf<2;mf++)
        #pragma unroll
        for (int nf=0;nf<8;nf++)
            #pragma unroll
            for (int q=0;q<4;q++) acc[mf][nf][q] = 0.0f;

    int r_ld = tid >> 2, j_ld = tid & 3;

    int a_row  = warpM*32 + (lane & 15);
    int a_coff = (lane >> 4) * 4;
    int b_row  = warpN*64 + (lane & 7);
    int b_coff = ((lane >> 3) & 1) * 4;

    // prologue: chunk 0 -> stage 0
    #pragma unroll
    for (int t = 0; t < 4; t++){
        const __nv_bfloat16* s0 = srcs[t];
        #pragma unroll
        for (int h = 0; h < 2; h++){
            int r = r_ld + h*64;
            cpasync16(sb + (t*PJ_TILE + r*PJ_STR + j_ld*4)*4,
                      s0 + (size_t)r*DD + j_ld*8);
        }
    }
    CP_COMMIT();

    for (int c = 0; c < 16; c++){
        int st = c & 1;
        CP_WAIT0();            // chunk c's group arrived (only one pending)
        __syncthreads();       // publishes data + guards stage st^1 reuse

        if (c + 1 < 16){       // issue chunk c+1 into st^1; lands during compute
            int k0 = (c+1) * 32;
            int so = (st^1) * 4;
            #pragma unroll
            for (int t = 0; t < 4; t++){
                const __nv_bfloat16* s0 = srcs[t];
                #pragma unroll
                for (int h = 0; h < 2; h++){
                    int r = r_ld + h*64;
                    cpasync16(sb + ((so+t)*PJ_TILE + r*PJ_STR + j_ld*4)*4,
                              s0 + (size_t)r*DD + k0 + j_ld*8);
                }
            }
            CP_COMMIT();
        }

        uint32_t sAhi = sb + ((st*4+0)*PJ_TILE)*4;
        uint32_t sAlo = sb + ((st*4+1)*PJ_TILE)*4;
        uint32_t sBhi = sb + ((st*4+2)*PJ_TILE)*4;
        uint32_t sBlo = sb + ((st*4+3)*PJ_TILE)*4;

        #pragma unroll
        for (int ks = 0; ks < 2; ks++){
            uint32_t ahi[2][4], alo[2][4];
            #pragma unroll
            for (int mf=0; mf<2; mf++){
                uint32_t off = (uint32_t)(((a_row + mf*16)*PJ_STR + a_coff + ks*8)*4);
                ldmA(ahi[mf], sAhi + off);
                ldmA(alo[mf], sAlo + off);
            }
            #pragma unroll
            for (int nf = 0; nf < 8; nf++){
                uint32_t boff = (uint32_t)(((b_row + nf*8)*PJ_STR + b_coff + ks*8)*4);
                uint32_t bh0, bh1, bl0, bl1;
                ldmB(bh0, bh1, sBhi + boff);
                ldmB(bl0, bl1, sBlo + boff);
                #pragma unroll
                for (int mf=0; mf<2; mf++){
                    mma16816(acc[mf][nf], ahi[mf], bh0, bh1);
                    mma16816(acc[mf][nf], ahi[mf], bl0, bl1);
                    mma16816(acc[mf][nf], alo[mf], bh0, bh1);
                }
            }
        }
    }

    #pragma unroll
    for (int mf = 0; mf < 2; mf++){
        int r0 = row0 + warpM*32 + mf*16 + g;
        #pragma unroll
        for (int nf = 0; nf < 8; nf++){
            int c0 = col0 + warpN*64 + nf*8 + tg*2;
            float b0 = bias[c0], b1 = bias[c0+1];
            float v00 = acc[mf][nf][0] + b0, v01 = acc[mf][nf][1] + b1;
            float v10 = acc[mf][nf][2] + b0, v11 = acc[mf][nf][3] + b1;
            dst[(size_t)r0*DD + c0]       = v00;
            dst[(size_t)r0*DD + c0 + 1]   = v01;
            dst[(size_t)(r0+8)*DD + c0]   = v10;
            dst[(size_t)(r0+8)*DD + c0+1] = v11;
            if (z < 2){
                dbf[(size_t)r0*DD + c0]       = __float2bfloat16(v00);
                dbf[(size_t)r0*DD + c0 + 1]   = __float2bfloat16(v01);
                dbf[(size_t)(r0+8)*DD + c0]   = __float2bfloat16(v10);
                dbf[(size_t)(r0+8)*DD + c0+1] = __float2bfloat16(v11);
            }
        }
    }
}

// ---------------- fused retrieve + attn bodies -------------------------------
// retrieve: CTA tile 128 x 208, KC=64, 2-stage cp.async, one barrier per chunk
#define RT_NT  208
#define RT_STR 36
#define RT_ROWS (128 + RT_NT)           // 336 staged rows
#define RT_STG (RT_ROWS*RT_STR)         // u32 per stage = 12096 (48,384 B)
#define ATTN_SMEM ((196*68 + 196*64) * (int)sizeof(float))   // 103,488 B

__device__ __forceinline__ void retrieve_body(int bx, char* smraw){
    uint32_t* smu = (uint32_t*)smraw;
    uint32_t sbase = (uint32_t)__cvta_generic_to_shared(smraw);
    float* s_rowred = (float*)(smu + 2*RT_STG);      // 128 f
    float* s_colred = s_rowred + 128;                // 208 f

    int tid = threadIdx.x;
    int lane = tid & 31, wid = tid >> 5;
    int g = lane >> 2, tg = lane & 3;
    int warpM = wid >> 1, warpN = wid & 1;

    int p = bx >> 1;                     // pair 0..1023
    int mtile = bx & 1;
    int a = p >> 5, b = p & 31;
    int row0 = mtile * 128;

    if (tid < 128)   s_rowred[tid] = -INFINITY;
    if (tid < RT_NT) s_colred[tid] = -INFINITY;

    const __nv_bfloat16* Abase = g_Qbf + (size_t)(a*LL)*DD;
    const __nv_bfloat16* Bbase = g_Kbf + (size_t)(b*LL)*DD;

    float acc[2][13][4];
    #pragma unroll
    for (int mf=0;mf<2;mf++)
        #pragma unroll
        for (int nf=0;nf<13;nf++)
            #pragma unroll
            for (int q=0;q<4;q++) acc[mf][nf][q] = 0.0f;

    auto stage_load = [&](int c, int s){
        uint32_t dst0 = sbase + (uint32_t)(s*RT_STG*4);
        int k0 = c * 64;
        for (int i = tid; i < RT_ROWS*8; i += 256){
            int r = i >> 3, j = i & 7;
            const __nv_bfloat16* src;
            if (r < 128){
                int grow = row0 + r; if (grow > LL-1) grow = LL-1;
                src = Abase + (size_t)grow*DD + k0 + j*8;
            } else {
                int grow = r - 128; if (grow > LL-1) grow = LL-1;
                src = Bbase + (size_t)grow*DD + k0 + j*8;
            }
            cpasync16(dst0 + (uint32_t)((r*RT_STR + j*4)*4), src);
        }
        CP_COMMIT();
    };

    stage_load(0, 0);

    for (int c = 0; c < 8; c++){
        int st = c & 1;
        CP_WAIT0();            // chunk c arrived
        __syncthreads();       // publish + stage-reuse guard

        if (c + 1 < 8) stage_load(c+1, st^1);   // overlaps compute below

        const uint32_t* Ast = smu + st*RT_STG;
        const uint32_t* Bst = Ast + 128*RT_STR;

        #pragma unroll
        for (int ks = 0; ks < 4; ks++){
            uint32_t afr[2][4];
            #pragma unroll
            for (int mf=0; mf<2; mf++){
                int r = warpM*32 + mf*16 + g;
                const uint32_t* ap = &Ast[r*RT_STR + ks*8 + tg];
                afr[mf][0] = ap[0];
                afr[mf][1] = ap[8*RT_STR];
                afr[mf][2] = ap[4];
                afr[mf][3] = ap[8*RT_STR + 4];
            }
            #pragma unroll
            for (int nf = 0; nf < 13; nf++){
                int n = warpN*104 + nf*8 + g;
                const uint32_t* bp = &Bst[n*RT_STR + ks*8 + tg];
                uint32_t b0 = bp[0];
                uint32_t b1 = bp[4];
                mma16816(acc[0][nf], afr[0], b0, b1);
                mma16816(acc[1][nf], afr[1], b0, b1);
            }
        }
    }
    __syncthreads();           // all compute done before epilogue reductions

    // ---- epilogue: element-wise masked max via shared atomics ----
    #pragma unroll
    for (int mf = 0; mf < 2; mf++){
        int lr  = warpM*32 + mf*16 + g;
        int gr0 = row0 + lr;
        int gr8 = gr0 + 8;
        #pragma unroll
        for (int nf = 0; nf < 13; nf++){
            int lc = warpN*104 + nf*8 + tg*2;     // = global column
            float c0 = acc[mf][nf][0], c1 = acc[mf][nf][1];
            float c2 = acc[mf][nf][2], c3 = acc[mf][nf][3];
            bool cv0 = (lc < LL), cv1 = (lc+1 < LL);
            bool rv0 = (gr0 < LL), rv8 = (gr8 < LL);

            float rm0 = -INFINITY, rm8 = -INFINITY;
            if (cv0){ rm0 = fmaxf(rm0, c0); rm8 = fmaxf(rm8, c2); }
            if (cv1){ rm0 = fmaxf(rm0, c1); rm8 = fmaxf(rm8, c3); }
            atomicMaxF(&s_rowred[lr],     rm0);
            atomicMaxF(&s_rowred[lr + 8], rm8);

            float cm0 = -INFINITY, cm1 = -INFINITY;
            if (rv0){ cm0 = fmaxf(cm0, c0); cm1 = fmaxf(cm1, c1); }
            if (rv8){ cm0 = fmaxf(cm0, c2); cm1 = fmaxf(cm1, c3); }
            if (cv0) atomicMaxF(&s_colred[lc],     cm0);
            if (cv1) atomicMaxF(&s_colred[lc + 1], cm1);
        }
    }
    __syncthreads();

    if (tid < 128){
        int grow = row0 + tid;
        if (grow < LL) atomicMaxF(&g_rowmax[(size_t)p*LL + grow], s_rowred[tid]);
    }
    if (tid < LL) atomicMaxF(&g_colmax[(size_t)p*LL + tid], s_colred[tid]);
}

// ---- attn body: 4 rows/warp, shuffle-P ctx ----------------------------------
__device__ __forceinline__ void attn_body(int h, int b, float* sm,
                                          float* __restrict__ out_probs){
    float* Ks  = sm;                 // [196][68]
    float* Vs  = sm + 196*68;        // [196][64]

    int tid = threadIdx.x;
    int w = tid >> 5, lane = tid & 31;

    const float* Kg = g_K + (size_t)(b*LL)*DD + h*DHH;
    const float* Vg = g_V + (size_t)(b*LL)*DD + h*DHH;

    for (int i = tid; i < LL*16; i += 256){
        int m = i >> 4, d4 = (i & 15) * 4;
        *(float4*)&Ks[m*68 + d4] = *(const float4*)(Kg + (size_t)m*DD + d4);
        *(float4*)&Vs[m*64 + d4] = *(const float4*)(Vg + (size_t)m*DD + d4);
    }
    __syncthreads();

    const float* Qb = g_Q + (size_t)(b*LL)*DD + h*DHH;

    int mm[7]; bool valid[7];
    #pragma unroll
    for (int mi=0;mi<7;mi++){
        int m = lane + mi*32;
        valid[mi] = (m < LL);
        mm[mi] = valid[mi] ? m : (LL-1);
    }

    for (int l0 = w*4; l0 < LL; l0 += 32){
        float s[4][7];
        #pragma unroll
        for (int li=0;li<4;li++)
            #pragma unroll
            for (int mi=0;mi<7;mi++) s[li][mi] = 0.0f;

        for (int d4 = 0; d4 < DHH; d4 += 4){
            float4 q0 = *(const float4*)(Qb + (size_t)(l0+0)*DD + d4);
            float4 q1 = *(const float4*)(Qb + (size_t)(l0+1)*DD + d4);
            float4 q2 = *(const float4*)(Qb + (size_t)(l0+2)*DD + d4);
            float4 q3 = *(const float4*)(Qb + (size_t)(l0+3)*DD + d4);
            #pragma unroll
            for (int mi=0;mi<7;mi++){
                float4 kf = *(const float4*)&Ks[mm[mi]*68 + d4];
                s[0][mi] += q0.x*kf.x + q0.y*kf.y + q0.z*kf.z + q0.w*kf.w;
                s[1][mi] += q1.x*kf.x + q1.y*kf.y + q1.z*kf.z + q1.w*kf.w;
                s[2][mi] += q2.x*kf.x + q2.y*kf.y + q2.z*kf.z + q2.w*kf.w;
                s[3][mi] += q3.x*kf.x + q3.y*kf.y + q3.z*kf.z + q3.w*kf.w;
            }
        }

        #pragma unroll
        for (int li=0;li<4;li++){
            float mx = -INFINITY;
            #pragma unroll
            for (int mi=0;mi<7;mi++){
                s[li][mi] = valid[mi] ? s[li][mi]*0.125f : -INFINITY;
                mx = fmaxf(mx, s[li][mi]);
            }
            #pragma unroll
            for (int o=16;o;o>>=1) mx = fmaxf(mx, __shfl_xor_sync(0xffffffffu, mx, o));
            float sum = 0.0f;
            #pragma unroll
            for (int mi=0;mi<7;mi++){ float e = expf(s[li][mi]-mx); s[li][mi]=e; sum+=e; }
            #pragma unroll
            for (int o=16;o;o>>=1) sum += __shfl_xor_sync(0xffffffffu, sum, o);
            float inv = 1.0f / sum;

            float* pmrow = out_probs + (size_t)(b*LL + l0 + li)*LL;
            #pragma unroll
            for (int mi=0;mi<7;mi++){
                s[li][mi] *= inv;
                if (valid[mi]) atomicAdd(&pmrow[mm[mi]], s[li][mi] * 0.125f);
            }
        }

        float c0x=0.f,c0y=0.f,c1x=0.f,c1y=0.f,c2x=0.f,c2y=0.f,c3x=0.f,c3y=0.f;
        for (int mi=0;mi<7;mi++){
            float p0r = s[0][mi], p1r = s[1][mi], p2r = s[2][mi], p3r = s[3][mi];
            #pragma unroll
            for (int ls=0; ls<32; ls++){
                int m = mi*32 + ls;
                float p0 = __shfl_sync(0xffffffffu, p0r, ls);
                float p1 = __shfl_sync(0xffffffffu, p1r, ls);
                float p2 = __shfl_sync(0xffffffffu, p2r, ls);
                float p3 = __shfl_sync(0xffffffffu, p3r, ls);
                if (m < LL){
                    float2 v2 = *(const float2*)&Vs[m*64 + lane*2];
                    c0x += p0*v2.x; c0y += p0*v2.y;
                    c1x += p1*v2.x; c1y += p1*v2.y;
                    c2x += p2*v2.x; c2y += p2*v2.y;
                    c3x += p3*v2.x; c3y += p3*v2.y;
                }
            }
        }
        float* cr = g_ctx + (size_t)(b*LL + l0)*DD + h*DHH + lane*2;
        cr[0]      = c0x; cr[1]      = c0y;
        cr[DD]     = c1x; cr[DD+1]   = c1y;
        cr[2*DD]   = c2x; cr[2*DD+1] = c2y;
        cr[3*DD]   = c3x; cr[3*DD+1] = c3y;
    }
}

// ---- fused launch: attn CTAs first (long, 1 wave), then retrieve CTAs -------
__global__ __launch_bounds__(256, 2) void fused_ra(float* __restrict__ out_probs){
    extern __shared__ char fsm[];
    if (blockIdx.x < HH*BB){
        attn_body(blockIdx.x & 7, blockIdx.x >> 3, (float*)fsm, out_probs);
    } else {
        retrieve_body(blockIdx.x - HH*BB, fsm);
    }
}

// ---------------- K3: logits reduce ------------------------------------------
__global__ __launch_bounds__(256) void logits_kernel(const float* __restrict__ ls,
                                                     float* __restrict__ out){
    int p = blockIdx.x;
    int t = threadIdx.x;
    float v = 0.0f;
    if (t < LL) v = g_rowmax[(size_t)p*LL + t] + g_colmax[(size_t)p*LL + t];
    #pragma unroll
    for (int o=16;o;o>>=1) v += __shfl_xor_sync(0xffffffffu, v, o);
    __shared__ float red[8];
    if ((t & 31) == 0) red[t >> 5] = v;
    __syncthreads();
    if (t == 0){
        float s = 0.0f;
        #pragma unroll
        for (int w=0; w<8; w++) s += red[w];
        out[p] = expf(ls[0]) * s / (2.0f * (float)LL);
    }
}

// ---------------- K5: residual + LayerNorm -----------------------------------
__global__ __launch_bounds__(128) void ln_kernel(const float* __restrict__ qin,
                                                 const float* __restrict__ gamma,
                                                 const float* __restrict__ beta,
                                                 float* __restrict__ out){
    int row = blockIdx.x;
    int t = threadIdx.x;
    const float* c = g_ctx + (size_t)row*DD;
    const float* q = qin   + (size_t)row*DD;
    __shared__ float red[4];

    float v[4]; float s = 0.0f;
    #pragma unroll
    for (int i=0;i<4;i++){ v[i] = c[t + i*128] + q[t + i*128]; s += v[i]; }
    #pragma unroll
    for (int o=16;o;o>>=1) s += __shfl_xor_sync(0xffffffffu, s, o);
    if ((t & 31) == 0) red[t>>5] = s;
    __syncthreads();
    float mu = (red[0]+red[1]+red[2]+red[3]) * (1.0f/DD);
    __syncthreads();

    float s2 = 0.0f;
    #pragma unroll
    for (int i=0;i<4;i++){ float d = v[i]-mu; s2 += d*d; }
    #pragma unroll
    for (int o=16;o;o>>=1) s2 += __shfl_xor_sync(0xffffffffu, s2, o);
    if ((t & 31) == 0) red[t>>5] = s2;
    __syncthreads();
    float var = (red[0]+red[1]+red[2]+red[3]) * (1.0f/DD);
    float invs = rsqrtf(var + 1e-6f);

    #pragma unroll
    for (int i=0;i<4;i++){
        int col = t + i*128;
        out[(size_t)row*DD + col] = (v[i]-mu)*invs*gamma[col] + beta[col];
    }
}

// ---------------- launch ------------------------------------------------------
extern "C" void kernel_launch(void* const* d_in, const int* in_sizes, int n_in,
                              void* d_out, int out_size)
{
    const float* q  = (const float*)d_in[0];
    const float* k  = (const float*)d_in[1];
    const float* v  = (const float*)d_in[2];
    const float* Wq = (const float*)d_in[3];
    const float* bq = (const float*)d_in[4];
    const float* Wk = (const float*)d_in[5];
    const float* bk = (const float*)d_in[6];
    const float* Wv = (const float*)d_in[7];
    const float* bv = (const float*)d_in[8];
    const float* gamma = (const float*)d_in[9];
    const float* beta  = (const float*)d_in[10];
    const float* ls    = (const float*)d_in[11];
    float* out = (float*)d_out;

    cudaFuncSetAttribute(fused_ra,    cudaFuncAttributeMaxDynamicSharedMemorySize, ATTN_SMEM);
    cudaFuncSetAttribute(proj_kernel, cudaFuncAttributeMaxDynamicSharedMemorySize, PJ_SMEM);

    init_kernel<<<(BB*BB*LL + 255)/256, 256>>>();
    cudaMemsetAsync(out + OUT_PROBS, 0, (size_t)BB*LL*LL*sizeof(float));

    split_x_kernel<<<dim3((MM*DD/4 + 255)/256, 1, 3), 256>>>(q, k, v);
    split_w_kernel<<<dim3((DD*DD/4 + 255)/256, 1, 3), 256>>>(Wq, Wk, Wv);

    proj_kernel<<<dim3(4, 49, 3), 256, PJ_SMEM>>>(bq, bk, bv);

    fused_ra<<<HH*BB + 2048, 256, ATTN_SMEM>>>(out + OUT_PROBS);

    logits_kernel<<<BB*BB, 256>>>(ls, out + OUT_LOGITS);

    ln_kernel<<<MM, 128>>>(q, gamma, beta, out + OUT_CTX);
}

// round 17
// speedup vs baseline: 1.3388x; 1.0917x over previous
#include <cuda_runtime.h>
#include <cuda_bf16.h>
#include <math.h>
#include <stdint.h>

#define BB 32
#define LL 196
#define DD 512
#define HH 8
#define DHH 64
#define MM (BB*LL)              // 6272

// ---------------- scratch (static device allocations; no malloc) -------------
__device__ float g_Q[MM*DD];
__device__ float g_K[MM*DD];
__device__ float g_V[MM*DD];
__device__ float g_ctx[MM*DD];
__device__ __nv_bfloat16 g_Qbf[MM*DD];
__device__ __nv_bfloat16 g_Kbf[MM*DD];
__device__ float g_rowmax[BB*BB*LL];
__device__ float g_colmax[BB*BB*LL];
// pre-split bf16 operands for the projection GEMM
__device__ __nv_bfloat16 g_Xhi[3*MM*DD];
__device__ __nv_bfloat16 g_Xlo[3*MM*DD];
__device__ __nv_bfloat16 g_Whi[3*DD*DD];
__device__ __nv_bfloat16 g_Wlo[3*DD*DD];

static const size_t OUT_CTX    = 0;
static const size_t OUT_LOGITS = (size_t)MM*DD;              // 3,211,264
static const size_t OUT_PROBS  = (size_t)MM*DD + BB*BB;      // 3,212,288

// float atomic max via signed/unsigned monotonicity trick (init = -inf)
__device__ __forceinline__ void atomicMaxF(float* addr, float v){
    if (v >= 0.0f) atomicMax((int*)addr, __float_as_int(v));
    else           atomicMin((unsigned int*)addr, __float_as_uint(v));
}

__device__ __forceinline__ void mma16816(float* d, const uint32_t* a,
                                         uint32_t b0, uint32_t b1){
    asm volatile("mma.sync.aligned.m16n8k16.row.col.f32.bf16.bf16.f32 "
        "{%0,%1,%2,%3}, {%4,%5,%6,%7}, {%8,%9}, {%0,%1,%2,%3};"
        : "+f"(d[0]), "+f"(d[1]), "+f"(d[2]), "+f"(d[3])
        : "r"(a[0]), "r"(a[1]), "r"(a[2]), "r"(a[3]), "r"(b0), "r"(b1));
}

__device__ __forceinline__ void ldmA(uint32_t* r, uint32_t saddr){
    asm volatile("ldmatrix.sync.aligned.m8n8.x4.shared.b16 {%0,%1,%2,%3}, [%4];"
        : "=r"(r[0]), "=r"(r[1]), "=r"(r[2]), "=r"(r[3]) : "r"(saddr));
}
__device__ __forceinline__ void ldmB(uint32_t& r0, uint32_t& r1, uint32_t saddr){
    asm volatile("ldmatrix.sync.aligned.m8n8.x2.shared.b16 {%0,%1}, [%2];"
        : "=r"(r0), "=r"(r1) : "r"(saddr));
}

__device__ __forceinline__ uint32_t packbf(__nv_bfloat16 a, __nv_bfloat16 b){
    __nv_bfloat162 t = __halves2bfloat162(a, b);
    return *(uint32_t*)&t;
}

__device__ __forceinline__ void cpasync16(uint32_t saddr, const void* gaddr){
    asm volatile("cp.async.cg.shared.global [%0], [%1], 16;"
                 :: "r"(saddr), "l"(gaddr) : "memory");
}
#define CP_COMMIT() asm volatile("cp.async.commit_group;" ::: "memory")
#define CP_WAIT0()  asm volatile("cp.async.wait_group 0;" ::: "memory")

// ---------------- K0: init row/col max scratch -------------------------------
__global__ void init_kernel(){
    int i = blockIdx.x*blockDim.x + threadIdx.x;
    if (i < BB*BB*LL){ g_rowmax[i] = -INFINITY; g_colmax[i] = -INFINITY; }
}

// ---------------- K0b: fp32 -> bf16 hi/lo split (X and W) --------------------
__global__ __launch_bounds__(256) void split_x_kernel(
    const float* __restrict__ Xq, const float* __restrict__ Xk, const float* __restrict__ Xv){
    int z = blockIdx.z;
    const float* src = (z==0)? Xq : (z==1)? Xk : Xv;
    __nv_bfloat16* hi = g_Xhi + (size_t)z*MM*DD;
    __nv_bfloat16* lo = g_Xlo + (size_t)z*MM*DD;
    size_t i = ((size_t)blockIdx.x*256 + threadIdx.x)*4;
    if (i < (size_t)MM*DD){
        float4 f = *(const float4*)(src + i);
        __nv_bfloat16 hx=__float2bfloat16(f.x), hy=__float2bfloat16(f.y);
        __nv_bfloat16 hz=__float2bfloat16(f.z), hw=__float2bfloat16(f.w);
        uint2 vh; vh.x = packbf(hx,hy); vh.y = packbf(hz,hw);
        *(uint2*)(hi + i) = vh;
        uint2 vl;
        vl.x = packbf(__float2bfloat16(f.x-__bfloat162float(hx)),
                      __float2bfloat16(f.y-__bfloat162float(hy)));
        vl.y = packbf(__float2bfloat16(f.z-__bfloat162float(hz)),
                      __float2bfloat16(f.w-__bfloat162float(hw)));
        *(uint2*)(lo + i) = vl;
    }
}

__global__ __launch_bounds__(256) void split_w_kernel(
    const float* __restrict__ Wq, const float* __restrict__ Wk, const float* __restrict__ Wv){
    int z = blockIdx.z;
    const float* src = (z==0)? Wq : (z==1)? Wk : Wv;
    __nv_bfloat16* hi = g_Whi + (size_t)z*DD*DD;
    __nv_bfloat16* lo = g_Wlo + (size_t)z*DD*DD;
    size_t i = ((size_t)blockIdx.x*256 + threadIdx.x)*4;
    if (i < (size_t)DD*DD){
        float4 f = *(const float4*)(src + i);
        __nv_bfloat16 hx=__float2bfloat16(f.x), hy=__float2bfloat16(f.y);
        __nv_bfloat16 hz=__float2bfloat16(f.z), hw=__float2bfloat16(f.w);
        uint2 vh; vh.x = packbf(hx,hy); vh.y = packbf(hz,hw);
        *(uint2*)(hi + i) = vh;
        uint2 vl;
        vl.x = packbf(__float2bfloat16(f.x-__bfloat162float(hx)),
                      __float2bfloat16(f.y-__bfloat162float(hy)));
        vl.y = packbf(__float2bfloat16(f.z-__bfloat162float(hz)),
                      __float2bfloat16(f.w-__bfloat162float(hw)));
        *(uint2*)(lo + i) = vl;
    }
}

// ---------------- K1: QKV projection via bf16x3 split mma --------------------
// cp.async 2-stage KC=32; ONE barrier per chunk (wait -> sync -> load-next -> compute).
#define PJ_STR 20
#define PJ_TILE (128*PJ_STR)
#define PJ_SMEM (8*PJ_TILE*4)           // 81920 B

__global__ __launch_bounds__(256, 2) void proj_kernel(
    const float* __restrict__ bq, const float* __restrict__ bk, const float* __restrict__ bv)
{
    int z = blockIdx.z;
    const float* bias = (z==0)? bq : (z==1)? bk : bv;
    float* dst = (z==0)? g_Q : (z==1)? g_K : g_V;
    __nv_bfloat16* dbf = (z==0)? g_Qbf : (z==1)? g_Kbf : (__nv_bfloat16*)0;

    extern __shared__ uint32_t psm[];
    uint32_t sb = (uint32_t)__cvta_generic_to_shared(psm);

    int tid = threadIdx.x;
    int lane = tid & 31, wid = tid >> 5;
    int g = lane >> 2, tg = lane & 3;
    int warpM = wid >> 1, warpN = wid & 1;

    int row0 = blockIdx.y * 128;
    int col0 = blockIdx.x * 128;

    const __nv_bfloat16* srcs[4] = {
        g_Xhi + (size_t)z*MM*DD + (size_t)row0*DD,
        g_Xlo + (size_t)z*MM*DD + (size_t)row0*DD,
        g_Whi + (size_t)z*DD*DD + (size_t)col0*DD,
        g_Wlo + (size_t)z*DD*DD + (size_t)col0*DD };

    float acc[2][8][4];
    #pragma unroll
    for (int mf=0;mf<2;mf++)
        #pragma unroll
        for (int nf=0;nf<8;nf++)
            #pragma unroll
            for (int q=0;q<4;q++) acc[mf][nf][q] = 0.0f;

    int r_ld = tid >> 2, j_ld = tid & 3;

    int a_row  = warpM*32 + (lane & 15);
    int a_coff = (lane >> 4) * 4;
    int b_row  = warpN*64 + (lane & 7);
    int b_coff = ((lane >> 3) & 1) * 4;

    // prologue: chunk 0 -> stage 0
    #pragma unroll
    for (int t = 0; t < 4; t++){
        const __nv_bfloat16* s0 = srcs[t];
        #pragma unroll
        for (int h = 0; h < 2; h++){
            int r = r_ld + h*64;
            cpasync16(sb + (t*PJ_TILE + r*PJ_STR + j_ld*4)*4,
                      s0 + (size_t)r*DD + j_ld*8);
        }
    }
    CP_COMMIT();

    for (int c = 0; c < 16; c++){
        int st = c & 1;
        CP_WAIT0();
        __syncthreads();

        if (c + 1 < 16){
            int k0 = (c+1) * 32;
            int so = (st^1) * 4;
            #pragma unroll
            for (int t = 0; t < 4; t++){
                const __nv_bfloat16* s0 = srcs[t];
                #pragma unroll
                for (int h = 0; h < 2; h++){
                    int r = r_ld + h*64;
                    cpasync16(sb + ((so+t)*PJ_TILE + r*PJ_STR + j_ld*4)*4,
                              s0 + (size_t)r*DD + k0 + j_ld*8);
                }
            }
            CP_COMMIT();
        }

        uint32_t sAhi = sb + ((st*4+0)*PJ_TILE)*4;
        uint32_t sAlo = sb + ((st*4+1)*PJ_TILE)*4;
        uint32_t sBhi = sb + ((st*4+2)*PJ_TILE)*4;
        uint32_t sBlo = sb + ((st*4+3)*PJ_TILE)*4;

        #pragma unroll
        for (int ks = 0; ks < 2; ks++){
            uint32_t ahi[2][4], alo[2][4];
            #pragma unroll
            for (int mf=0; mf<2; mf++){
                uint32_t off = (uint32_t)(((a_row + mf*16)*PJ_STR + a_coff + ks*8)*4);
                ldmA(ahi[mf], sAhi + off);
                ldmA(alo[mf], sAlo + off);
            }
            #pragma unroll
            for (int nf = 0; nf < 8; nf++){
                uint32_t boff = (uint32_t)(((b_row + nf*8)*PJ_STR + b_coff + ks*8)*4);
                uint32_t bh0, bh1, bl0, bl1;
                ldmB(bh0, bh1, sBhi + boff);
                ldmB(bl0, bl1, sBlo + boff);
                #pragma unroll
                for (int mf=0; mf<2; mf++){
                    mma16816(acc[mf][nf], ahi[mf], bh0, bh1);
                    mma16816(acc[mf][nf], ahi[mf], bl0, bl1);
                    mma16816(acc[mf][nf], alo[mf], bh0, bh1);
                }
            }
        }
    }

    #pragma unroll
    for (int mf = 0; mf < 2; mf++){
        int r0 = row0 + warpM*32 + mf*16 + g;
        #pragma unroll
        for (int nf = 0; nf < 8; nf++){
            int c0 = col0 + warpN*64 + nf*8 + tg*2;
            float b0 = bias[c0], b1 = bias[c0+1];
            float v00 = acc[mf][nf][0] + b0, v01 = acc[mf][nf][1] + b1;
            float v10 = acc[mf][nf][2] + b0, v11 = acc[mf][nf][3] + b1;
            dst[(size_t)r0*DD + c0]       = v00;
            dst[(size_t)r0*DD + c0 + 1]   = v01;
            dst[(size_t)(r0+8)*DD + c0]   = v10;
            dst[(size_t)(r0+8)*DD + c0+1] = v11;
            if (z < 2){
                dbf[(size_t)r0*DD + c0]       = __float2bfloat16(v00);
                dbf[(size_t)r0*DD + c0 + 1]   = __float2bfloat16(v01);
                dbf[(size_t)(r0+8)*DD + c0]   = __float2bfloat16(v10);
                dbf[(size_t)(r0+8)*DD + c0+1] = __float2bfloat16(v11);
            }
        }
    }
}

// ---------------- fused retrieve + attn bodies -------------------------------
// retrieve: CTA tile 128 x 208, KC=64, 2-stage cp.async, one barrier per chunk
#define RT_NT  208
#define RT_STR 36
#define RT_ROWS (128 + RT_NT)           // 336 staged rows
#define RT_STG (RT_ROWS*RT_STR)         // u32 per stage = 12096 (48,384 B)
#define ATTN_SMEM ((196*68 + 196*64) * (int)sizeof(float))   // 103,488 B

__device__ __forceinline__ void retrieve_body(int bx, char* smraw){
    uint32_t* smu = (uint32_t*)smraw;
    uint32_t sbase = (uint32_t)__cvta_generic_to_shared(smraw);
    float* s_rowred = (float*)(smu + 2*RT_STG);      // 128 f
    float* s_colred = s_rowred + 128;                // 208 f

    int tid = threadIdx.x;
    int lane = tid & 31, wid = tid >> 5;
    int g = lane >> 2, tg = lane & 3;
    int warpM = wid >> 1, warpN = wid & 1;

    int p = bx >> 1;                     // pair 0..1023
    int mtile = bx & 1;
    int a = p >> 5, b = p & 31;
    int row0 = mtile * 128;

    if (tid < 128)   s_rowred[tid] = -INFINITY;
    if (tid < RT_NT) s_colred[tid] = -INFINITY;

    const __nv_bfloat16* Abase = g_Qbf + (size_t)(a*LL)*DD;
    const __nv_bfloat16* Bbase = g_Kbf + (size_t)(b*LL)*DD;

    float acc[2][13][4];
    #pragma unroll
    for (int mf=0;mf<2;mf++)
        #pragma unroll
        for (int nf=0;nf<13;nf++)
            #pragma unroll
            for (int q=0;q<4;q++) acc[mf][nf][q] = 0.0f;

    auto stage_load = [&](int c, int s){
        uint32_t dst0 = sbase + (uint32_t)(s*RT_STG*4);
        int k0 = c * 64;
        for (int i = tid; i < RT_ROWS*8; i += 256){
            int r = i >> 3, j = i & 7;
            const __nv_bfloat16* src;
            if (r < 128){
                int grow = row0 + r; if (grow > LL-1) grow = LL-1;
                src = Abase + (size_t)grow*DD + k0 + j*8;
            } else {
                int grow = r - 128; if (grow > LL-1) grow = LL-1;
                src = Bbase + (size_t)grow*DD + k0 + j*8;
            }
            cpasync16(dst0 + (uint32_t)((r*RT_STR + j*4)*4), src);
        }
        CP_COMMIT();
    };

    stage_load(0, 0);

    for (int c = 0; c < 8; c++){
        int st = c & 1;
        CP_WAIT0();
        __syncthreads();

        if (c + 1 < 8) stage_load(c+1, st^1);

        const uint32_t* Ast = smu + st*RT_STG;
        const uint32_t* Bst = Ast + 128*RT_STR;

        #pragma unroll
        for (int ks = 0; ks < 4; ks++){
            uint32_t afr[2][4];
            #pragma unroll
            for (int mf=0; mf<2; mf++){
                int r = warpM*32 + mf*16 + g;
                const uint32_t* ap = &Ast[r*RT_STR + ks*8 + tg];
                afr[mf][0] = ap[0];
                afr[mf][1] = ap[8*RT_STR];
                afr[mf][2] = ap[4];
                afr[mf][3] = ap[8*RT_STR + 4];
            }
            #pragma unroll
            for (int nf = 0; nf < 13; nf++){
                int n = warpN*104 + nf*8 + g;
                const uint32_t* bp = &Bst[n*RT_STR + ks*8 + tg];
                uint32_t b0 = bp[0];
                uint32_t b1 = bp[4];
                mma16816(acc[0][nf], afr[0], b0, b1);
                mma16816(acc[1][nf], afr[1], b0, b1);
            }
        }
    }
    __syncthreads();

    // ---- epilogue: element-wise masked max via shared atomics ----
    #pragma unroll
    for (int mf = 0; mf < 2; mf++){
        int lr  = warpM*32 + mf*16 + g;
        int gr0 = row0 + lr;
        int gr8 = gr0 + 8;
        #pragma unroll
        for (int nf = 0; nf < 13; nf++){
            int lc = warpN*104 + nf*8 + tg*2;     // = global column
            float c0 = acc[mf][nf][0], c1 = acc[mf][nf][1];
            float c2 = acc[mf][nf][2], c3 = acc[mf][nf][3];
            bool cv0 = (lc < LL), cv1 = (lc+1 < LL);
            bool rv0 = (gr0 < LL), rv8 = (gr8 < LL);

            float rm0 = -INFINITY, rm8 = -INFINITY;
            if (cv0){ rm0 = fmaxf(rm0, c0); rm8 = fmaxf(rm8, c2); }
            if (cv1){ rm0 = fmaxf(rm0, c1); rm8 = fmaxf(rm8, c3); }
            atomicMaxF(&s_rowred[lr],     rm0);
            atomicMaxF(&s_rowred[lr + 8], rm8);

            float cm0 = -INFINITY, cm1 = -INFINITY;
            if (rv0){ cm0 = fmaxf(cm0, c0); cm1 = fmaxf(cm1, c1); }
            if (rv8){ cm0 = fmaxf(cm0, c2); cm1 = fmaxf(cm1, c3); }
            if (cv0) atomicMaxF(&s_colred[lc],     cm0);
            if (cv1) atomicMaxF(&s_colred[lc + 1], cm1);
        }
    }
    __syncthreads();

    if (tid < 128){
        int grow = row0 + tid;
        if (grow < LL) atomicMaxF(&g_rowmax[(size_t)p*LL + grow], s_rowred[tid]);
    }
    if (tid < LL) atomicMaxF(&g_colmax[(size_t)p*LL + tid], s_colred[tid]);
}

// ---- attn body: 4 rows/warp, shuffle-P ctx ----------------------------------
__device__ __forceinline__ void attn_body(int h, int b, float* sm,
                                          float* __restrict__ out_probs){
    float* Ks  = sm;                 // [196][68]
    float* Vs  = sm + 196*68;        // [196][64]

    int tid = threadIdx.x;
    int w = tid >> 5, lane = tid & 31;

    const float* Kg = g_K + (size_t)(b*LL)*DD + h*DHH;
    const float* Vg = g_V + (size_t)(b*LL)*DD + h*DHH;

    for (int i = tid; i < LL*16; i += 256){
        int m = i >> 4, d4 = (i & 15) * 4;
        *(float4*)&Ks[m*68 + d4] = *(const float4*)(Kg + (size_t)m*DD + d4);
        *(float4*)&Vs[m*64 + d4] = *(const float4*)(Vg + (size_t)m*DD + d4);
    }
    __syncthreads();

    const float* Qb = g_Q + (size_t)(b*LL)*DD + h*DHH;

    int mm[7]; bool valid[7];
    #pragma unroll
    for (int mi=0;mi<7;mi++){
        int m = lane + mi*32;
        valid[mi] = (m < LL);
        mm[mi] = valid[mi] ? m : (LL-1);
    }

    for (int l0 = w*4; l0 < LL; l0 += 32){
        float s[4][7];
        #pragma unroll
        for (int li=0;li<4;li++)
            #pragma unroll
            for (int mi=0;mi<7;mi++) s[li][mi] = 0.0f;

        for (int d4 = 0; d4 < DHH; d4 += 4){
            float4 q0 = *(const float4*)(Qb + (size_t)(l0+0)*DD + d4);
            float4 q1 = *(const float4*)(Qb + (size_t)(l0+1)*DD + d4);
            float4 q2 = *(const float4*)(Qb + (size_t)(l0+2)*DD + d4);
            float4 q3 = *(const float4*)(Qb + (size_t)(l0+3)*DD + d4);
            #pragma unroll
            for (int mi=0;mi<7;mi++){
                float4 kf = *(const float4*)&Ks[mm[mi]*68 + d4];
                s[0][mi] += q0.x*kf.x + q0.y*kf.y + q0.z*kf.z + q0.w*kf.w;
                s[1][mi] += q1.x*kf.x + q1.y*kf.y + q1.z*kf.z + q1.w*kf.w;
                s[2][mi] += q2.x*kf.x + q2.y*kf.y + q2.z*kf.z + q2.w*kf.w;
                s[3][mi] += q3.x*kf.x + q3.y*kf.y + q3.z*kf.z + q3.w*kf.w;
            }
        }

        #pragma unroll
        for (int li=0;li<4;li++){
            float mx = -INFINITY;
            #pragma unroll
            for (int mi=0;mi<7;mi++){
                s[li][mi] = valid[mi] ? s[li][mi]*0.125f : -INFINITY;
                mx = fmaxf(mx, s[li][mi]);
            }
            #pragma unroll
            for (int o=16;o;o>>=1) mx = fmaxf(mx, __shfl_xor_sync(0xffffffffu, mx, o));
            float sum = 0.0f;
            #pragma unroll
            for (int mi=0;mi<7;mi++){ float e = expf(s[li][mi]-mx); s[li][mi]=e; sum+=e; }
            #pragma unroll
            for (int o=16;o;o>>=1) sum += __shfl_xor_sync(0xffffffffu, sum, o);
            float inv = 1.0f / sum;

            float* pmrow = out_probs + (size_t)(b*LL + l0 + li)*LL;
            #pragma unroll
            for (int mi=0;mi<7;mi++){
                s[li][mi] *= inv;
                if (valid[mi]) atomicAdd(&pmrow[mm[mi]], s[li][mi] * 0.125f);
            }
        }

        float c0x=0.f,c0y=0.f,c1x=0.f,c1y=0.f,c2x=0.f,c2y=0.f,c3x=0.f,c3y=0.f;
        for (int mi=0;mi<7;mi++){
            float p0r = s[0][mi], p1r = s[1][mi], p2r = s[2][mi], p3r = s[3][mi];
            #pragma unroll
            for (int ls=0; ls<32; ls++){
                int m = mi*32 + ls;
                float p0 = __shfl_sync(0xffffffffu, p0r, ls);
                float p1 = __shfl_sync(0xffffffffu, p1r, ls);
                float p2 = __shfl_sync(0xffffffffu, p2r, ls);
                float p3 = __shfl_sync(0xffffffffu, p3r, ls);
                if (m < LL){
                    float2 v2 = *(const float2*)&Vs[m*64 + lane*2];
                    c0x += p0*v2.x; c0y += p0*v2.y;
                    c1x += p1*v2.x; c1y += p1*v2.y;
                    c2x += p2*v2.x; c2y += p2*v2.y;
                    c3x += p3*v2.x; c3y += p3*v2.y;
                }
            }
        }
        float* cr = g_ctx + (size_t)(b*LL + l0)*DD + h*DHH + lane*2;
        cr[0]      = c0x; cr[1]      = c0y;
        cr[DD]     = c1x; cr[DD+1]   = c1y;
        cr[2*DD]   = c2x; cr[2*DD+1] = c2y;
        cr[3*DD]   = c3x; cr[3*DD+1] = c3y;
    }
}

// ---- fused launch: attn CTAs interleaved 1:3 among retrieve CTAs ------------
// bid < 1024: (bid&3)==0 -> attn idx bid>>2 (covers 0..255); else retrieve.
// bid >= 1024: retrieve. retrieve idx formulas partition 0..2047 exactly.
__global__ __launch_bounds__(256, 2) void fused_ra(float* __restrict__ out_probs){
    extern __shared__ char fsm[];
    int bid = blockIdx.x;
    if (bid < 1024){
        if ((bid & 3) == 0){
            int ai = bid >> 2;                  // 0..255
            attn_body(ai & 7, ai >> 3, (float*)fsm, out_probs);
        } else {
            int ri = bid - 1 - (bid >> 2);      // 0..767
            retrieve_body(ri, fsm);
        }
    } else {
        retrieve_body(bid - 256, fsm);          // 768..2047
    }
}

// ---------------- K3: logits reduce ------------------------------------------
__global__ __launch_bounds__(256) void logits_kernel(const float* __restrict__ ls,
                                                     float* __restrict__ out){
    int p = blockIdx.x;
    int t = threadIdx.x;
    float v = 0.0f;
    if (t < LL) v = g_rowmax[(size_t)p*LL + t] + g_colmax[(size_t)p*LL + t];
    #pragma unroll
    for (int o=16;o;o>>=1) v += __shfl_xor_sync(0xffffffffu, v, o);
    __shared__ float red[8];
    if ((t & 31) == 0) red[t >> 5] = v;
    __syncthreads();
    if (t == 0){
        float s = 0.0f;
        #pragma unroll
        for (int w=0; w<8; w++) s += red[w];
        out[p] = expf(ls[0]) * s / (2.0f * (float)LL);
    }
}

// ---------------- K5: residual + LayerNorm -----------------------------------
__global__ __launch_bounds__(128) void ln_kernel(const float* __restrict__ qin,
                                                 const float* __restrict__ gamma,
                                                 const float* __restrict__ beta,
                                                 float* __restrict__ out){
    int row = blockIdx.x;
    int t = threadIdx.x;
    const float* c = g_ctx + (size_t)row*DD;
    const float* q = qin   + (size_t)row*DD;
    __shared__ float red[4];

    float v[4]; float s = 0.0f;
    #pragma unroll
    for (int i=0;i<4;i++){ v[i] = c[t + i*128] + q[t + i*128]; s += v[i]; }
    #pragma unroll
    for (int o=16;o;o>>=1) s += __shfl_xor_sync(0xffffffffu, s, o);
    if ((t & 31) == 0) red[t>>5] = s;
    __syncthreads();
    float mu = (red[0]+red[1]+red[2]+red[3]) * (1.0f/DD);
    __syncthreads();

    float s2 = 0.0f;
    #pragma unroll
    for (int i=0;i<4;i++){ float d = v[i]-mu; s2 += d*d; }
    #pragma unroll
    for (int o=16;o;o>>=1) s2 += __shfl_xor_sync(0xffffffffu, s2, o);
    if ((t & 31) == 0) red[t>>5] = s2;
    __syncthreads();
    float var = (red[0]+red[1]+red[2]+red[3]) * (1.0f/DD);
    float invs = rsqrtf(var + 1e-6f);

    #pragma unroll
    for (int i=0;i<4;i++){
        int col = t + i*128;
        out[(size_t)row*DD + col] = (v[i]-mu)*invs*gamma[col] + beta[col];
    }
}

// ---------------- launch ------------------------------------------------------
extern "C" void kernel_launch(void* const* d_in, const int* in_sizes, int n_in,
                              void* d_out, int out_size)
{
    const float* q  = (const float*)d_in[0];
    const float* k  = (const float*)d_in[1];
    const float* v  = (const float*)d_in[2];
    const float* Wq = (const float*)d_in[3];
    const float* bq = (const float*)d_in[4];
    const float* Wk = (const float*)d_in[5];
    const float* bk = (const float*)d_in[6];
    const float* Wv = (const float*)d_in[7];
    const float* bv = (const float*)d_in[8];
    const float* gamma = (const float*)d_in[9];
    const float* beta  = (const float*)d_in[10];
    const float* ls    = (const float*)d_in[11];
    float* out = (float*)d_out;

    cudaFuncSetAttribute(fused_ra,    cudaFuncAttributeMaxDynamicSharedMemorySize, ATTN_SMEM);
    cudaFuncSetAttribute(proj_kernel, cudaFuncAttributeMaxDynamicSharedMemorySize, PJ_SMEM);

    init_kernel<<<(BB*BB*LL + 255)/256, 256>>>();
    cudaMemsetAsync(out + OUT_PROBS, 0, (size_t)BB*LL*LL*sizeof(float));

    split_x_kernel<<<dim3((MM*DD/4 + 255)/256, 1, 3), 256>>>(q, k, v);
    split_w_kernel<<<dim3((DD*DD/4 + 255)/256, 1, 3), 256>>>(Wq, Wk, Wv);

    proj_kernel<<<dim3(4, 49, 3), 256, PJ_SMEM>>>(bq, bk, bv);

    fused_ra<<<HH*BB + 2048, 256, ATTN_SMEM>>>(out + OUT_PROBS);

    logits_kernel<<<BB*BB, 256>>>(ls, out + OUT_LOGITS);

    ln_kernel<<<MM, 128>>>(q, gamma, beta, out + OUT_CTX);
}